// round 2
// baseline (speedup 1.0000x reference)
#include <cuda_runtime.h>

#define B_   8
#define N_   207
#define T_   12
#define C_   64
#define L_   2484
#define LPAD 2496
#define NTILE 39

// ---------------- scratch (module globals; zero-initialized) ----------------
__device__ float g_h[B_ * LPAD * C_];   // [b][l][c]
__device__ float g_q[B_ * LPAD * 8];    // [b][l][d]
__device__ float g_k[B_ * LPAD * 8];    // [b][m][d]
__device__ float g_v[B_ * LPAD * C_];   // [b][m][c]

// packed f32x2 FMA (Blackwell): d = a*b + c elementwise on 2 packed floats
__device__ __forceinline__ float2 ffma2(float2 a, float2 b, float2 c) {
    float2 d;
    asm("fma.rn.f32x2 %0, %1, %2, %3;"
        : "=l"(reinterpret_cast<unsigned long long&>(d))
        : "l"(reinterpret_cast<unsigned long long&>(a)),
          "l"(reinterpret_cast<unsigned long long&>(b)),
          "l"(reinterpret_cast<unsigned long long&>(c)));
    return d;
}

// ---------------------------------------------------------------------------
// Kernel 1: causal conv (x2) + GLU gate + q/k/v projections, fused per l-tile
// grid (NTILE, B), 512 threads, ~186KB dynamic smem (1 block/SM)
// ---------------------------------------------------------------------------
__global__ void __launch_bounds__(512, 1)
k1_conv_qkv(const float* __restrict__ X,
            const float* __restrict__ wA, const float* __restrict__ bA,
            const float* __restrict__ wB, const float* __restrict__ bB,
            const float* __restrict__ wq, const float* __restrict__ bq,
            const float* __restrict__ wk, const float* __restrict__ bk,
            const float* __restrict__ wv, const float* __restrict__ bv)
{
    extern __shared__ float smem[];
    float* wAs = smem;              // [idx=k*64+ci][c]  12288
    float* wBs = smem + 12288;      // 12288
    float* xs  = smem + 24576;      // [l][pitch 193]    12352
    float* hs  = smem + 36928;      // [c][pitch 65]     4160
    float* wvS = smem + 41088;      // [c][pitch 68]     4352
    float* wqS = smem + 45440;      // [d*64+c]          512
    float* wkS = smem + 45952;      // 512
    float* bAs = smem + 46464;      // 64
    float* bBs = smem + 46528;      // 64
    float* bvS = smem + 46592;      // 64
    float* bqS = smem + 46656;      // 8
    float* bkS = smem + 46664;      // 8   (total 46672 floats)

    const int tid = threadIdx.x;
    const int b   = blockIdx.y;
    const int l0  = blockIdx.x * 64;

    // ---- stage weights ----
    for (int e = tid; e < 12288; e += 512) {
        int c = e & 63, idxp = e >> 6;
        int k = idxp >> 6, ci = idxp & 63;
        int src = (c * 64 + ci) * 3 + k;
        wAs[e] = wA[src];
        wBs[e] = wB[src];
    }
    for (int e = tid; e < 4096; e += 512) {
        int o = e >> 6, c = e & 63;
        wvS[c * 68 + o] = wv[e];
    }
    if (tid < 512) { wqS[tid] = wq[tid]; wkS[tid] = wk[tid]; }
    if (tid < 64)       { bAs[tid] = bA[tid]; bBs[tid] = bB[tid]; bvS[tid] = bv[tid]; }
    else if (tid < 72)  { bqS[tid - 64] = bq[tid - 64]; bkS[tid - 64] = bk[tid - 64]; }

    // ---- stage conv taps: xs[l][k*64+ci] = X[b][n][t-2+k][ci] (0 if causal-clipped) ----
    for (int e = tid; e < 64 * 192; e += 512) {
        int l = e / 192, r = e - l * 192;
        int k = r >> 6, ci = r & 63;
        int gl = l0 + l;
        float v = 0.f;
        if (gl < L_) {
            int n = gl / 12, t = gl - n * 12;
            int tt = t - 2 + k;
            if (tt >= 0) v = X[((b * N_ + n) * T_ + tt) * C_ + ci];
        }
        xs[l * 193 + r] = v;
    }
    __syncthreads();

    // ---- conv GEMM: 4c x 2l register tile per thread, f32x2 packed ----
    const int cb = (tid & 15) * 4;
    const int lb = (tid >> 4) * 2;
    float2 aA[2][2], aB[2][2];
    #pragma unroll
    for (int i = 0; i < 2; i++)
        #pragma unroll
        for (int j = 0; j < 2; j++) { aA[i][j] = make_float2(0.f, 0.f); aB[i][j] = make_float2(0.f, 0.f); }

    #pragma unroll 4
    for (int p = 0; p < 192; p++) {
        float4 wa = *(const float4*)&wAs[p * 64 + cb];
        float4 wb = *(const float4*)&wBs[p * 64 + cb];
        float2 wa0 = make_float2(wa.x, wa.y), wa1 = make_float2(wa.z, wa.w);
        float2 wb0 = make_float2(wb.x, wb.y), wb1 = make_float2(wb.z, wb.w);
        #pragma unroll
        for (int j = 0; j < 2; j++) {
            float xv = xs[(lb + j) * 193 + p];
            float2 xx = make_float2(xv, xv);
            aA[0][j] = ffma2(wa0, xx, aA[0][j]);
            aA[1][j] = ffma2(wa1, xx, aA[1][j]);
            aB[0][j] = ffma2(wb0, xx, aB[0][j]);
            aB[1][j] = ffma2(wb1, xx, aB[1][j]);
        }
    }

    // ---- gate: h = (A+bA) * sigmoid(B+bB) -> hs[c][l] ----
    #pragma unroll
    for (int i2 = 0; i2 < 2; i2++) {
        int c0 = cb + i2 * 2;
        #pragma unroll
        for (int j = 0; j < 2; j++) {
            float a0 = aA[i2][j].x + bAs[c0];
            float a1 = aA[i2][j].y + bAs[c0 + 1];
            float g0 = aB[i2][j].x + bBs[c0];
            float g1 = aB[i2][j].y + bBs[c0 + 1];
            float h0 = a0 / (1.f + __expf(-g0));
            float h1 = a1 / (1.f + __expf(-g1));
            hs[c0 * 65 + lb + j]       = h0;
            hs[(c0 + 1) * 65 + lb + j] = h1;
        }
    }
    __syncthreads();

    // ---- write h to gmem as [b][l][c] (residual for epilogue) ----
    for (int e = tid; e < 4096; e += 512) {
        int l = e >> 6, c = e & 63;
        int gl = l0 + l;
        if (gl < L_) g_h[((size_t)b * LPAD + gl) * 64 + c] = hs[c * 65 + l];
    }

    // ---- v = wv @ h + bv  (4o x 2l per thread, f32x2) ----
    float2 vacc[2][2];
    #pragma unroll
    for (int i = 0; i < 2; i++)
        #pragma unroll
        for (int j = 0; j < 2; j++) vacc[i][j] = make_float2(0.f, 0.f);

    #pragma unroll 4
    for (int c = 0; c < 64; c++) {
        float4 w4 = *(const float4*)&wvS[c * 68 + cb];
        float2 w0 = make_float2(w4.x, w4.y), w1 = make_float2(w4.z, w4.w);
        #pragma unroll
        for (int j = 0; j < 2; j++) {
            float hv = hs[c * 65 + lb + j];
            float2 hh = make_float2(hv, hv);
            vacc[0][j] = ffma2(w0, hh, vacc[0][j]);
            vacc[1][j] = ffma2(w1, hh, vacc[1][j]);
        }
    }
    #pragma unroll
    for (int j = 0; j < 2; j++) {
        int gl = l0 + lb + j;
        float4 o;
        o.x = vacc[0][j].x + bvS[cb];
        o.y = vacc[0][j].y + bvS[cb + 1];
        o.z = vacc[1][j].x + bvS[cb + 2];
        o.w = vacc[1][j].y + bvS[cb + 3];
        if (gl >= L_) o = make_float4(0.f, 0.f, 0.f, 0.f);
        *(float4*)&g_v[((size_t)b * LPAD + gl) * 64 + cb] = o;
    }

    // ---- q,k: each thread one l, one d per head tensor ----
    {
        int lq = tid & 63, dd = tid >> 6;       // dd in 0..7
        float aq = 0.f, ak = 0.f;
        const float* wqr = &wqS[dd * 64];
        const float* wkr = &wkS[dd * 64];
        #pragma unroll 8
        for (int c = 0; c < 64; c++) {
            float hv = hs[c * 65 + lq];
            aq += wqr[c] * hv;
            ak += wkr[c] * hv;
        }
        int gl = l0 + lq;
        float q0 = aq + bqS[dd];
        float k0 = ak + bkS[dd];
        if (gl >= L_) { q0 = 0.f; k0 = 0.f; }
        size_t base = ((size_t)b * LPAD + gl) * 8;
        g_q[base + dd] = q0;
        g_k[base + dd] = k0;
    }
}

// ---------------------------------------------------------------------------
// Kernel 2: flash-style attention + residual epilogue
// grid (NTILE, B), 512 threads = 64 rows x 8 groups (8 j-scores / 8 channels)
// ~39KB smem, <=64 regs -> 2 blocks/SM -> 32 warps/SM
// ---------------------------------------------------------------------------
__global__ void __launch_bounds__(512, 2)
k2_attn(const float* __restrict__ gamma, float* __restrict__ out)
{
    __shared__ float kS[64 * 8];        // [j][d]
    __shared__ float vS[64 * 64];       // [j][c]
    __shared__ float pS[64 * 65];       // [row][j], pitch 65
    __shared__ float lmS[8 * 64];       // [ty][row]
    __shared__ float psS[8 * 64];       // [ty][row]

    const int tid = threadIdx.x;
    const int tx  = tid & 63;           // query row within tile
    const int ty  = tid >> 6;           // octile: scores j-group and accum ch-group
    const int b   = blockIdx.y;
    const int l0  = blockIdx.x * 64;
    const int gl  = l0 + tx;
    const int ob  = ty * 8;

    float qv[8];
    {
        const float4* qp = (const float4*)&g_q[((size_t)b * LPAD + gl) * 8];
        float4 q0 = qp[0], q1 = qp[1];
        qv[0] = q0.x; qv[1] = q0.y; qv[2] = q0.z; qv[3] = q0.w;
        qv[4] = q1.x; qv[5] = q1.y; qv[6] = q1.z; qv[7] = q1.w;
    }

    float mx = -1e30f, ssum = 0.f;
    float2 acc[4];
    #pragma unroll
    for (int i = 0; i < 4; i++) acc[i] = make_float2(0.f, 0.f);

    for (int m0 = 0; m0 < L_; m0 += 64) {
        __syncthreads();   // protect smem reuse across iterations
        if (tid < 128)
            *(float4*)&kS[tid * 4] = *(const float4*)&g_k[((size_t)b * LPAD + m0) * 8 + tid * 4];
        {
            const float4* vsrc = (const float4*)&g_v[((size_t)b * LPAD + m0) * 64];
            float4* vdst = (float4*)vS;
            vdst[tid]       = vsrc[tid];
            vdst[tid + 512] = vsrc[tid + 512];
        }
        __syncthreads();

        const int mvalid = L_ - m0;

        // scores for this thread's j-octile (computed exactly once)
        float s[8];
        float lm = -1e30f;
        #pragma unroll
        for (int jj = 0; jj < 8; jj++) {
            int j = ty * 8 + jj;
            float4 k0 = *(const float4*)&kS[j * 8];
            float4 k1 = *(const float4*)&kS[j * 8 + 4];
            float d = qv[0] * k0.x + qv[1] * k0.y + qv[2] * k0.z + qv[3] * k0.w
                    + qv[4] * k1.x + qv[5] * k1.y + qv[6] * k1.z + qv[7] * k1.w;
            if (j >= mvalid) d = -1e30f;
            s[jj] = d;
            lm = fmaxf(lm, d);
        }
        lmS[ty * 64 + tx] = lm;
        __syncthreads();

        float tmax = lmS[tx];
        #pragma unroll
        for (int i = 1; i < 8; i++) tmax = fmaxf(tmax, lmS[i * 64 + tx]);
        float nmx  = fmaxf(mx, tmax);
        float corr = __expf(mx - nmx);
        mx = nmx;

        float ps = 0.f;
        #pragma unroll
        for (int jj = 0; jj < 8; jj++) {
            float p = __expf(s[jj] - nmx);
            ps += p;
            pS[tx * 65 + ty * 8 + jj] = p;
        }
        psS[ty * 64 + tx] = ps;
        ssum *= corr;
        #pragma unroll
        for (int i = 0; i < 4; i++) { acc[i].x *= corr; acc[i].y *= corr; }
        __syncthreads();

        #pragma unroll
        for (int i = 0; i < 8; i++) ssum += psS[i * 64 + tx];

        // v accumulation: 8 channels per thread, f32x2 packed
        const float* prow = &pS[tx * 65];
        #pragma unroll 8
        for (int j = 0; j < 64; j++) {
            float pj = prow[j];
            float2 pp = make_float2(pj, pj);
            const float4* vr = (const float4*)&vS[j * 64 + ob];
            float4 v0 = vr[0], v1 = vr[1];
            acc[0] = ffma2(pp, make_float2(v0.x, v0.y), acc[0]);
            acc[1] = ffma2(pp, make_float2(v0.z, v0.w), acc[1]);
            acc[2] = ffma2(pp, make_float2(v1.x, v1.y), acc[2]);
            acc[3] = ffma2(pp, make_float2(v1.z, v1.w), acc[3]);
        }
    }

    if (gl < L_) {
        float inv = 1.f / ssum;
        float g = gamma[0];
        const float4* hsrc = (const float4*)&g_h[((size_t)b * LPAD + gl) * 64 + ob];
        float4* dst = (float4*)&out[((size_t)b * L_ + gl) * 64 + ob];
        #pragma unroll
        for (int i = 0; i < 2; i++) {
            float4 h4 = hsrc[i];
            float4 o;
            o.x = g * (acc[2 * i].x     * inv) + h4.x;
            o.y = g * (acc[2 * i].y     * inv) + h4.y;
            o.z = g * (acc[2 * i + 1].x * inv) + h4.z;
            o.w = g * (acc[2 * i + 1].y * inv) + h4.w;
            dst[i] = o;
        }
    }
}

// ---------------------------------------------------------------------------
extern "C" void kernel_launch(void* const* d_in, const int* in_sizes, int n_in,
                              void* d_out, int out_size)
{
    const float* X     = (const float*)d_in[0];
    const float* wA    = (const float*)d_in[1];
    const float* bA    = (const float*)d_in[2];
    const float* wB    = (const float*)d_in[3];
    const float* bB    = (const float*)d_in[4];
    const float* wq    = (const float*)d_in[5];
    const float* bq    = (const float*)d_in[6];
    const float* wk    = (const float*)d_in[7];
    const float* bk    = (const float*)d_in[8];
    const float* wv    = (const float*)d_in[9];
    const float* bv    = (const float*)d_in[10];
    const float* gamma = (const float*)d_in[11];
    float* out = (float*)d_out;

    const size_t smem1 = 46672 * sizeof(float);   // ~186.7 KB
    cudaFuncSetAttribute(k1_conv_qkv, cudaFuncAttributeMaxDynamicSharedMemorySize, (int)smem1);

    dim3 grid(NTILE, B_);
    k1_conv_qkv<<<grid, 512, smem1>>>(X, wA, bA, wB, bB, wq, bq, wk, bk, wv, bv);
    k2_attn<<<grid, 512>>>(gamma, out);
}

// round 4
// speedup vs baseline: 1.5819x; 1.5819x over previous
#include <cuda_runtime.h>

#define B_   8
#define N_   207
#define T_   12
#define C_   64
#define L_   2484
#define LPAD 2496
#define NTILE 39

// ---------------- scratch (module globals) ----------------
__device__ float g_h[B_ * LPAD * C_];   // [b][l][c]
__device__ float g_q[B_ * LPAD * 8];    // [b][l][d]
__device__ float g_k[B_ * LPAD * 8];    // [b][m][d]
__device__ float g_v[B_ * LPAD * C_];   // [b][m][c]
__device__ float g_wAT[192 * 64];       // [p=k*64+ci][c]
__device__ float g_wBT[192 * 64];
__device__ float g_wvT[64 * 64];        // [c][o]

// packed f32x2 FMA (Blackwell)
__device__ __forceinline__ float2 ffma2(float2 a, float2 b, float2 c) {
    float2 d;
    asm("fma.rn.f32x2 %0, %1, %2, %3;"
        : "=l"(reinterpret_cast<unsigned long long&>(d))
        : "l"(reinterpret_cast<unsigned long long&>(a)),
          "l"(reinterpret_cast<unsigned long long&>(b)),
          "l"(reinterpret_cast<unsigned long long&>(c)));
    return d;
}

// ---------------------------------------------------------------------------
// Kernel 0: weight transposes (tiny, runs once per launch)
// ---------------------------------------------------------------------------
__global__ void k0_transpose(const float* __restrict__ wA,
                             const float* __restrict__ wB,
                             const float* __restrict__ wv)
{
    int t = blockIdx.x * 256 + threadIdx.x;
    if (t < 12288) {
        int p = t >> 6, c = t & 63;       // p = k*64 + ci
        int k = p >> 6, ci = p & 63;
        int src = (c * 64 + ci) * 3 + k;
        g_wAT[t] = wA[src];
        g_wBT[t] = wB[src];
    }
    if (t < 4096) {
        int c = t >> 6, o = t & 63;
        g_wvT[t] = wv[o * 64 + c];
    }
}

// ---------------------------------------------------------------------------
// Kernel 1: causal conv (x2) + GLU gate + q/k/v projections
// grid (NTILE, B), 256 threads, ~71KB dyn smem -> 3 blocks/SM
// ---------------------------------------------------------------------------
__global__ void __launch_bounds__(256, 3)
k1_conv_qkv(const float* __restrict__ X,
            const float* __restrict__ bA, const float* __restrict__ bB,
            const float* __restrict__ wq, const float* __restrict__ bq,
            const float* __restrict__ wk, const float* __restrict__ bk,
            const float* __restrict__ bv)
{
    extern __shared__ float smem[];
    float* xs  = smem;               // [l][pitch 193]  12352
    float* hs  = smem + 12352;       // [c][pitch 65]   4160
    float* wqS = smem + 16512;       // 512
    float* wkS = smem + 17024;       // 512
    float* bAs = smem + 17536;       // 64
    float* bBs = smem + 17600;       // 64
    float* bvS = smem + 17664;       // 64
    float* bqS = smem + 17728;       // 8
    float* bkS = smem + 17736;       // 8   total 17744 floats (~71KB)

    const int tid = threadIdx.x;
    const int b   = blockIdx.y;
    const int l0  = blockIdx.x * 64;

    // ---- stage small weights/biases ----
    { int e = tid;        wqS[e] = wq[e]; wkS[e] = wk[e];
      e = tid + 256;      wqS[e] = wq[e]; wkS[e] = wk[e]; }
    if (tid < 64)      { bAs[tid] = bA[tid]; bBs[tid] = bB[tid]; bvS[tid] = bv[tid]; }
    else if (tid < 72) { bqS[tid - 64] = bq[tid - 64]; bkS[tid - 64] = bk[tid - 64]; }

    // ---- stage conv taps: xs[l][k*64+ci] ----
    for (int e = tid; e < 64 * 192; e += 256) {
        int l = e / 192, r = e - l * 192;
        int k = r >> 6, ci = r & 63;
        int gl = l0 + l;
        float v = 0.f;
        if (gl < L_) {
            int n = gl / 12, t = gl - n * 12;
            int tt = t - 2 + k;
            if (tt >= 0) v = X[((b * N_ + n) * T_ + tt) * C_ + ci];
        }
        xs[l * 193 + r] = v;
    }
    __syncthreads();

    // ---- conv GEMM: 4c x 4l per thread, weights via LDG (L1-resident) ----
    const int cb = (tid & 15) * 4;
    const int lb = (tid >> 4) * 4;
    float2 aA[2][4], aB[2][4];
    #pragma unroll
    for (int i = 0; i < 2; i++)
        #pragma unroll
        for (int j = 0; j < 4; j++) { aA[i][j] = make_float2(0.f, 0.f); aB[i][j] = make_float2(0.f, 0.f); }

    #pragma unroll 4
    for (int p = 0; p < 192; p++) {
        float4 wa = __ldg((const float4*)&g_wAT[p * 64 + cb]);
        float4 wb = __ldg((const float4*)&g_wBT[p * 64 + cb]);
        float2 wa0 = make_float2(wa.x, wa.y), wa1 = make_float2(wa.z, wa.w);
        float2 wb0 = make_float2(wb.x, wb.y), wb1 = make_float2(wb.z, wb.w);
        #pragma unroll
        for (int j = 0; j < 4; j++) {
            float xv = xs[(lb + j) * 193 + p];
            float2 xx = make_float2(xv, xv);
            aA[0][j] = ffma2(wa0, xx, aA[0][j]);
            aA[1][j] = ffma2(wa1, xx, aA[1][j]);
            aB[0][j] = ffma2(wb0, xx, aB[0][j]);
            aB[1][j] = ffma2(wb1, xx, aB[1][j]);
        }
    }

    // ---- gate: h = (A+bA) * sigmoid(B+bB) -> hs[c][l] ----
    #pragma unroll
    for (int i2 = 0; i2 < 2; i2++) {
        int c0 = cb + i2 * 2;
        #pragma unroll
        for (int j = 0; j < 4; j++) {
            float a0 = aA[i2][j].x + bAs[c0];
            float a1 = aA[i2][j].y + bAs[c0 + 1];
            float g0 = aB[i2][j].x + bBs[c0];
            float g1 = aB[i2][j].y + bBs[c0 + 1];
            hs[c0 * 65 + lb + j]       = a0 / (1.f + __expf(-g0));
            hs[(c0 + 1) * 65 + lb + j] = a1 / (1.f + __expf(-g1));
        }
    }
    __syncthreads();

    // ---- write h to gmem as [b][l][c] ----
    for (int e = tid; e < 4096; e += 256) {
        int l = e >> 6, c = e & 63;
        int gl = l0 + l;
        if (gl < L_) g_h[((size_t)b * LPAD + gl) * 64 + c] = hs[c * 65 + l];
    }

    // ---- v = wv @ h + bv (4o x 4l per thread) ----
    float2 vacc[2][4];
    #pragma unroll
    for (int i = 0; i < 2; i++)
        #pragma unroll
        for (int j = 0; j < 4; j++) vacc[i][j] = make_float2(0.f, 0.f);

    #pragma unroll 4
    for (int c = 0; c < 64; c++) {
        float4 w4 = __ldg((const float4*)&g_wvT[c * 64 + cb]);
        float2 w0 = make_float2(w4.x, w4.y), w1 = make_float2(w4.z, w4.w);
        #pragma unroll
        for (int j = 0; j < 4; j++) {
            float hv = hs[c * 65 + lb + j];
            float2 hh = make_float2(hv, hv);
            vacc[0][j] = ffma2(w0, hh, vacc[0][j]);
            vacc[1][j] = ffma2(w1, hh, vacc[1][j]);
        }
    }
    #pragma unroll
    for (int j = 0; j < 4; j++) {
        int gl = l0 + lb + j;
        float4 o;
        o.x = vacc[0][j].x + bvS[cb];
        o.y = vacc[0][j].y + bvS[cb + 1];
        o.z = vacc[1][j].x + bvS[cb + 2];
        o.w = vacc[1][j].y + bvS[cb + 3];
        if (gl >= L_) o = make_float4(0.f, 0.f, 0.f, 0.f);
        *(float4*)&g_v[((size_t)b * LPAD + gl) * 64 + cb] = o;
    }

    // ---- q,k: each thread one l, two d-values per tensor ----
    {
        int lq = tid & 63, dd = tid >> 6;       // dd 0..3 -> d=dd and d=dd+4
        float aq0 = 0.f, aq1 = 0.f, ak0 = 0.f, ak1 = 0.f;
        const float* wq0 = &wqS[dd * 64];       const float* wq1 = &wqS[(dd + 4) * 64];
        const float* wk0 = &wkS[dd * 64];       const float* wk1 = &wkS[(dd + 4) * 64];
        #pragma unroll 4
        for (int c = 0; c < 64; c++) {
            float hv = hs[c * 65 + lq];
            aq0 += wq0[c] * hv; aq1 += wq1[c] * hv;
            ak0 += wk0[c] * hv; ak1 += wk1[c] * hv;
        }
        int gl = l0 + lq;
        float q0 = aq0 + bqS[dd], q1 = aq1 + bqS[dd + 4];
        float k0 = ak0 + bkS[dd], k1 = ak1 + bkS[dd + 4];
        if (gl >= L_) { q0 = q1 = k0 = k1 = 0.f; }
        size_t base = ((size_t)b * LPAD + gl) * 8;
        g_q[base + dd] = q0; g_q[base + dd + 4] = q1;
        g_k[base + dd] = k0; g_k[base + dd + 4] = k1;
    }
}

// ---------------------------------------------------------------------------
// Kernel 2: flash attention, register-tiled P@V (4x4 per thread)
// grid (NTILE, B), 256 threads, ~38KB smem, 3 blocks/SM
// pT pitch = 64 (16B-aligned rows; reads are 16 distinct float4 -> no conflicts)
// ---------------------------------------------------------------------------
__global__ void __launch_bounds__(256, 3)
k2_attn(const float* __restrict__ gamma, float* __restrict__ out)
{
    __shared__ float kS[64 * 8];      // [j][d]
    __shared__ float vS[64 * 64];     // [j][c]
    __shared__ float pT[64 * 64];     // [j][row], pitch 64 (aligned)
    __shared__ float lmS[4 * 64];
    __shared__ float psS[4 * 64];
    __shared__ float corrS[64];
    __shared__ float ssumS[64];

    const int tid = threadIdx.x;
    const int tx  = tid & 63;         // softmax view: query row
    const int ty  = tid >> 6;         // softmax view: j-quarter (16 j each)
    const int r0  = (tid & 15) * 4;   // tiled view: 4 output rows
    const int c0  = (tid >> 4) * 4;   // tiled view: 4 output cols
    const int b   = blockIdx.y;
    const int l0  = blockIdx.x * 64;

    float qv[8];
    {
        const float4* qp = (const float4*)&g_q[((size_t)b * LPAD + l0 + tx) * 8];
        float4 q0 = qp[0], q1 = qp[1];
        qv[0] = q0.x; qv[1] = q0.y; qv[2] = q0.z; qv[3] = q0.w;
        qv[4] = q1.x; qv[5] = q1.y; qv[6] = q1.z; qv[7] = q1.w;
    }

    float mx = -1e30f, ssum = 0.f;
    float2 acc[4][2];                 // [row i][col pair]
    #pragma unroll
    for (int i = 0; i < 4; i++) { acc[i][0] = make_float2(0.f, 0.f); acc[i][1] = make_float2(0.f, 0.f); }

    for (int m0 = 0; m0 < L_; m0 += 64) {
        __syncthreads();   // guard smem reuse (prev accum done)
        if (tid < 128)
            *(float4*)&kS[tid * 4] = *(const float4*)&g_k[((size_t)b * LPAD + m0) * 8 + tid * 4];
        {
            const float4* vsrc = (const float4*)&g_v[((size_t)b * LPAD + m0) * 64];
            float4* vdst = (float4*)vS;
            #pragma unroll
            for (int u = 0; u < 4; u++) vdst[u * 256 + tid] = vsrc[u * 256 + tid];
        }
        __syncthreads();

        const int mvalid = L_ - m0;

        // ---- scores: 16 j per thread ----
        float s[16];
        float lm = -1e30f;
        #pragma unroll
        for (int jj = 0; jj < 16; jj++) {
            int j = ty * 16 + jj;
            float4 k0 = *(const float4*)&kS[j * 8];
            float4 k1 = *(const float4*)&kS[j * 8 + 4];
            float d = qv[0] * k0.x + qv[1] * k0.y + qv[2] * k0.z + qv[3] * k0.w
                    + qv[4] * k1.x + qv[5] * k1.y + qv[6] * k1.z + qv[7] * k1.w;
            if (j >= mvalid) d = -1e30f;
            s[jj] = d;
            lm = fmaxf(lm, d);
        }
        lmS[ty * 64 + tx] = lm;
        __syncthreads();

        float tmax = fmaxf(fmaxf(lmS[tx], lmS[64 + tx]), fmaxf(lmS[128 + tx], lmS[192 + tx]));
        float nmx  = fmaxf(mx, tmax);
        float corr = __expf(mx - nmx);
        mx = nmx;

        float ps = 0.f;
        #pragma unroll
        for (int jj = 0; jj < 16; jj++) {
            float p = __expf(s[jj] - nmx);
            ps += p;
            pT[(ty * 16 + jj) * 64 + tx] = p;   // transposed: [j][row]
        }
        psS[ty * 64 + tx] = ps;
        if (ty == 0) corrS[tx] = corr;
        __syncthreads();

        ssum = ssum * corr + psS[tx] + psS[64 + tx] + psS[128 + tx] + psS[192 + tx];

        // ---- tiled accum: rescale rows, then 4x4 GEMM tile ----
        {
            float cr0 = corrS[r0], cr1 = corrS[r0 + 1], cr2 = corrS[r0 + 2], cr3 = corrS[r0 + 3];
            acc[0][0].x *= cr0; acc[0][0].y *= cr0; acc[0][1].x *= cr0; acc[0][1].y *= cr0;
            acc[1][0].x *= cr1; acc[1][0].y *= cr1; acc[1][1].x *= cr1; acc[1][1].y *= cr1;
            acc[2][0].x *= cr2; acc[2][0].y *= cr2; acc[2][1].x *= cr2; acc[2][1].y *= cr2;
            acc[3][0].x *= cr3; acc[3][0].y *= cr3; acc[3][1].x *= cr3; acc[3][1].y *= cr3;
        }
        #pragma unroll 4
        for (int j = 0; j < 64; j++) {
            float4 p4 = *(const float4*)&pT[j * 64 + r0];
            float4 v4 = *(const float4*)&vS[j * 64 + c0];
            float2 vlo = make_float2(v4.x, v4.y), vhi = make_float2(v4.z, v4.w);
            float2 pp0 = make_float2(p4.x, p4.x);
            float2 pp1 = make_float2(p4.y, p4.y);
            float2 pp2 = make_float2(p4.z, p4.z);
            float2 pp3 = make_float2(p4.w, p4.w);
            acc[0][0] = ffma2(pp0, vlo, acc[0][0]); acc[0][1] = ffma2(pp0, vhi, acc[0][1]);
            acc[1][0] = ffma2(pp1, vlo, acc[1][0]); acc[1][1] = ffma2(pp1, vhi, acc[1][1]);
            acc[2][0] = ffma2(pp2, vlo, acc[2][0]); acc[2][1] = ffma2(pp2, vhi, acc[2][1]);
            acc[3][0] = ffma2(pp3, vlo, acc[3][0]); acc[3][1] = ffma2(pp3, vhi, acc[3][1]);
        }
    }

    if (ty == 0) ssumS[tx] = ssum;
    __syncthreads();

    const float g = gamma[0];
    #pragma unroll
    for (int i = 0; i < 4; i++) {
        int row = r0 + i;
        int gl  = l0 + row;
        if (gl < L_) {
            float inv = 1.f / ssumS[row];
            float4 h4 = *(const float4*)&g_h[((size_t)b * LPAD + gl) * 64 + c0];
            float4 o;
            o.x = g * (acc[i][0].x * inv) + h4.x;
            o.y = g * (acc[i][0].y * inv) + h4.y;
            o.z = g * (acc[i][1].x * inv) + h4.z;
            o.w = g * (acc[i][1].y * inv) + h4.w;
            *(float4*)&out[((size_t)b * L_ + gl) * 64 + c0] = o;
        }
    }
}

// ---------------------------------------------------------------------------
extern "C" void kernel_launch(void* const* d_in, const int* in_sizes, int n_in,
                              void* d_out, int out_size)
{
    const float* X     = (const float*)d_in[0];
    const float* wA    = (const float*)d_in[1];
    const float* bA    = (const float*)d_in[2];
    const float* wB    = (const float*)d_in[3];
    const float* bB    = (const float*)d_in[4];
    const float* wq    = (const float*)d_in[5];
    const float* bq    = (const float*)d_in[6];
    const float* wk    = (const float*)d_in[7];
    const float* bk    = (const float*)d_in[8];
    const float* wv    = (const float*)d_in[9];
    const float* bv    = (const float*)d_in[10];
    const float* gamma = (const float*)d_in[11];
    float* out = (float*)d_out;

    const size_t smem1 = 17744 * sizeof(float);   // ~71KB
    cudaFuncSetAttribute(k1_conv_qkv, cudaFuncAttributeMaxDynamicSharedMemorySize, (int)smem1);

    dim3 grid(NTILE, B_);
    k0_transpose<<<48, 256>>>(wA, wB, wv);
    k1_conv_qkv<<<grid, 256, smem1>>>(X, bA, bB, wq, bq, wk, bk, bv);
    k2_attn<<<grid, 256>>>(gamma, out);
}

// round 6
// speedup vs baseline: 1.6523x; 1.0445x over previous
#include <cuda_runtime.h>
#include <cstdint>

#define B_   8
#define N_   207
#define T_   12
#define C_   64
#define L_   2484
#define LPAD 2496
#define NTILE 39

// ---------------- scratch (module globals) ----------------
__device__ float g_h[B_ * LPAD * C_];   // [b][l][c]
__device__ float g_q[B_ * LPAD * 8];    // [b][l][d]
__device__ float g_k[B_ * LPAD * 8];    // [b][m][d]
__device__ float g_v[B_ * LPAD * C_];   // [b][m][c]
__device__ float g_wAT[192 * 64];       // [p=k*64+ci][c]
__device__ float g_wBT[192 * 64];
__device__ float g_wvT[64 * 64];        // [c][o]

// packed f32x2 FMA / MUL (Blackwell)
__device__ __forceinline__ float2 ffma2(float2 a, float2 b, float2 c) {
    float2 d;
    asm("fma.rn.f32x2 %0, %1, %2, %3;"
        : "=l"(reinterpret_cast<unsigned long long&>(d))
        : "l"(reinterpret_cast<unsigned long long&>(a)),
          "l"(reinterpret_cast<unsigned long long&>(b)),
          "l"(reinterpret_cast<unsigned long long&>(c)));
    return d;
}
__device__ __forceinline__ float2 fmul2(float2 a, float2 b) {
    float2 d;
    asm("mul.rn.f32x2 %0, %1, %2;"
        : "=l"(reinterpret_cast<unsigned long long&>(d))
        : "l"(reinterpret_cast<unsigned long long&>(a)),
          "l"(reinterpret_cast<unsigned long long&>(b)));
    return d;
}

__device__ __forceinline__ void cp16(unsigned int saddr, const void* gaddr) {
    asm volatile("cp.async.ca.shared.global [%0], [%1], 16;" :: "r"(saddr), "l"(gaddr));
}
__device__ __forceinline__ void cp_commit() {
    asm volatile("cp.async.commit_group;" ::: "memory");
}
__device__ __forceinline__ void cp_wait0() {
    asm volatile("cp.async.wait_group 0;" ::: "memory");
}

// ---------------------------------------------------------------------------
// Kernel 0: weight transposes (tiny, runs once per launch)
// ---------------------------------------------------------------------------
__global__ void k0_transpose(const float* __restrict__ wA,
                             const float* __restrict__ wB,
                             const float* __restrict__ wv)
{
    int t = blockIdx.x * 256 + threadIdx.x;
    if (t < 12288) {
        int p = t >> 6, c = t & 63;       // p = k*64 + ci
        int k = p >> 6, ci = p & 63;
        int src = (c * 64 + ci) * 3 + k;
        g_wAT[t] = wA[src];
        g_wBT[t] = wB[src];
    }
    if (t < 4096) {
        int c = t >> 6, o = t & 63;
        g_wvT[t] = wv[o * 64 + c];
    }
}

// ---------------------------------------------------------------------------
// Kernel 1: causal conv (x2) + GLU gate + q/k/v projections
// grid (NTILE, B), 256 threads, ~71KB dyn smem -> 3 blocks/SM
// ---------------------------------------------------------------------------
__global__ void __launch_bounds__(256, 3)
k1_conv_qkv(const float* __restrict__ X,
            const float* __restrict__ bA, const float* __restrict__ bB,
            const float* __restrict__ wq, const float* __restrict__ bq,
            const float* __restrict__ wk, const float* __restrict__ bk,
            const float* __restrict__ bv)
{
    extern __shared__ float smem[];
    float* xs  = smem;               // [l][pitch 193]  12352
    float* hs  = smem + 12352;       // [c][pitch 65]   4160
    float* wqS = smem + 16512;       // 512
    float* wkS = smem + 17024;       // 512
    float* bAs = smem + 17536;       // 64
    float* bBs = smem + 17600;       // 64
    float* bvS = smem + 17664;       // 64
    float* bqS = smem + 17728;       // 8
    float* bkS = smem + 17736;       // 8   total 17744 floats (~71KB)

    const int tid = threadIdx.x;
    const int b   = blockIdx.y;
    const int l0  = blockIdx.x * 64;

    // ---- stage small weights/biases ----
    { int e = tid;        wqS[e] = wq[e]; wkS[e] = wk[e];
      e = tid + 256;      wqS[e] = wq[e]; wkS[e] = wk[e]; }
    if (tid < 64)      { bAs[tid] = bA[tid]; bBs[tid] = bB[tid]; bvS[tid] = bv[tid]; }
    else if (tid < 72) { bqS[tid - 64] = bq[tid - 64]; bkS[tid - 64] = bk[tid - 64]; }

    // ---- stage conv taps: xs[l][k*64+ci] ----
    for (int e = tid; e < 64 * 192; e += 256) {
        int l = e / 192, r = e - l * 192;
        int k = r >> 6, ci = r & 63;
        int gl = l0 + l;
        float v = 0.f;
        if (gl < L_) {
            int n = gl / 12, t = gl - n * 12;
            int tt = t - 2 + k;
            if (tt >= 0) v = X[((b * N_ + n) * T_ + tt) * C_ + ci];
        }
        xs[l * 193 + r] = v;
    }
    __syncthreads();

    // ---- conv GEMM: 4c x 4l per thread, weights via LDG (L1-resident) ----
    const int cb = (tid & 15) * 4;
    const int lb = (tid >> 4) * 4;
    float2 aA[2][4], aB[2][4];
    #pragma unroll
    for (int i = 0; i < 2; i++)
        #pragma unroll
        for (int j = 0; j < 4; j++) { aA[i][j] = make_float2(0.f, 0.f); aB[i][j] = make_float2(0.f, 0.f); }

    #pragma unroll 4
    for (int p = 0; p < 192; p++) {
        float4 wa = __ldg((const float4*)&g_wAT[p * 64 + cb]);
        float4 wb = __ldg((const float4*)&g_wBT[p * 64 + cb]);
        float2 wa0 = make_float2(wa.x, wa.y), wa1 = make_float2(wa.z, wa.w);
        float2 wb0 = make_float2(wb.x, wb.y), wb1 = make_float2(wb.z, wb.w);
        #pragma unroll
        for (int j = 0; j < 4; j++) {
            float xv = xs[(lb + j) * 193 + p];
            float2 xx = make_float2(xv, xv);
            aA[0][j] = ffma2(wa0, xx, aA[0][j]);
            aA[1][j] = ffma2(wa1, xx, aA[1][j]);
            aB[0][j] = ffma2(wb0, xx, aB[0][j]);
            aB[1][j] = ffma2(wb1, xx, aB[1][j]);
        }
    }

    // ---- gate: h = (A+bA) * sigmoid(B+bB) -> hs[c][l] ----
    #pragma unroll
    for (int i2 = 0; i2 < 2; i2++) {
        int c0 = cb + i2 * 2;
        #pragma unroll
        for (int j = 0; j < 4; j++) {
            float a0 = aA[i2][j].x + bAs[c0];
            float a1 = aA[i2][j].y + bAs[c0 + 1];
            float g0 = aB[i2][j].x + bBs[c0];
            float g1 = aB[i2][j].y + bBs[c0 + 1];
            hs[c0 * 65 + lb + j]       = a0 / (1.f + __expf(-g0));
            hs[(c0 + 1) * 65 + lb + j] = a1 / (1.f + __expf(-g1));
        }
    }
    __syncthreads();

    // ---- write h to gmem as [b][l][c] ----
    for (int e = tid; e < 4096; e += 256) {
        int l = e >> 6, c = e & 63;
        int gl = l0 + l;
        if (gl < L_) g_h[((size_t)b * LPAD + gl) * 64 + c] = hs[c * 65 + l];
    }

    // ---- v = wv @ h + bv (4o x 4l per thread) ----
    float2 vacc[2][4];
    #pragma unroll
    for (int i = 0; i < 2; i++)
        #pragma unroll
        for (int j = 0; j < 4; j++) vacc[i][j] = make_float2(0.f, 0.f);

    #pragma unroll 4
    for (int c = 0; c < 64; c++) {
        float4 w4 = __ldg((const float4*)&g_wvT[c * 64 + cb]);
        float2 w0 = make_float2(w4.x, w4.y), w1 = make_float2(w4.z, w4.w);
        #pragma unroll
        for (int j = 0; j < 4; j++) {
            float hv = hs[c * 65 + lb + j];
            float2 hh = make_float2(hv, hv);
            vacc[0][j] = ffma2(w0, hh, vacc[0][j]);
            vacc[1][j] = ffma2(w1, hh, vacc[1][j]);
        }
    }
    #pragma unroll
    for (int j = 0; j < 4; j++) {
        int gl = l0 + lb + j;
        float4 o;
        o.x = vacc[0][j].x + bvS[cb];
        o.y = vacc[0][j].y + bvS[cb + 1];
        o.z = vacc[1][j].x + bvS[cb + 2];
        o.w = vacc[1][j].y + bvS[cb + 3];
        if (gl >= L_) o = make_float4(0.f, 0.f, 0.f, 0.f);
        *(float4*)&g_v[((size_t)b * LPAD + gl) * 64 + cb] = o;
    }

    // ---- q,k: each thread one l, two d-values per tensor ----
    {
        int lq = tid & 63, dd = tid >> 6;       // dd 0..3 -> d=dd and d=dd+4
        float aq0 = 0.f, aq1 = 0.f, ak0 = 0.f, ak1 = 0.f;
        const float* wq0 = &wqS[dd * 64];       const float* wq1 = &wqS[(dd + 4) * 64];
        const float* wk0 = &wkS[dd * 64];       const float* wk1 = &wkS[(dd + 4) * 64];
        #pragma unroll 4
        for (int c = 0; c < 64; c++) {
            float hv = hs[c * 65 + lq];
            aq0 += wq0[c] * hv; aq1 += wq1[c] * hv;
            ak0 += wk0[c] * hv; ak1 += wk1[c] * hv;
        }
        int gl = l0 + lq;
        float q0 = aq0 + bqS[dd], q1 = aq1 + bqS[dd + 4];
        float k0 = ak0 + bkS[dd], k1 = ak1 + bkS[dd + 4];
        if (gl >= L_) { q0 = q1 = k0 = k1 = 0.f; }
        size_t base = ((size_t)b * LPAD + gl) * 8;
        g_q[base + dd] = q0; g_q[base + dd + 4] = q1;
        g_k[base + dd] = k0; g_k[base + dd + 4] = k1;
    }
}

// ---------------------------------------------------------------------------
// Kernel 2: flash attention, register-tiled 4x4 P@V,
// cp.async double-buffered k/v tiles, packed-f32x2 scores.
// grid (NTILE, B), 256 threads, ~54KB smem
// ---------------------------------------------------------------------------
__global__ void __launch_bounds__(256, 3)
k2_attn(const float* __restrict__ gamma, float* __restrict__ out)
{
    __shared__ float kS[2][64 * 8];   // [buf][j][d]
    __shared__ float vS[2][64 * 64];  // [buf][j][c]
    __shared__ float pT[64 * 64];     // [j][row]
    __shared__ float lmS[4 * 64];
    __shared__ float psS[4 * 64];
    __shared__ float corrS[64];
    __shared__ float ssumS[64];

    const int tid = threadIdx.x;
    const int tx  = tid & 63;         // softmax view: query row
    const int ty  = tid >> 6;         // softmax view: j-quarter (16 j each)
    const int r0  = (tid & 15) * 4;   // tiled view: 4 output rows
    const int c0  = (tid >> 4) * 4;   // tiled view: 4 output cols
    const int b   = blockIdx.y;
    const int l0  = blockIdx.x * 64;

    // smem u32 addresses for cp.async destinations owned by this thread
    unsigned int kDst[2], vDst[2];
    {
        unsigned int kbase0 = (unsigned int)__cvta_generic_to_shared(&kS[0][0]);
        unsigned int kbase1 = (unsigned int)__cvta_generic_to_shared(&kS[1][0]);
        unsigned int vbase0 = (unsigned int)__cvta_generic_to_shared(&vS[0][0]);
        unsigned int vbase1 = (unsigned int)__cvta_generic_to_shared(&vS[1][0]);
        kDst[0] = kbase0 + tid * 16;  kDst[1] = kbase1 + tid * 16;   // tid<128 only
        vDst[0] = vbase0 + tid * 16;  vDst[1] = vbase1 + tid * 16;   // + u*4096
    }

    // prologue: issue loads for tile 0 into buf 0
    {
        const char* kg = (const char*)&g_k[((size_t)b * LPAD + 0) * 8] + tid * 16;
        const char* vg = (const char*)&g_v[((size_t)b * LPAD + 0) * 64] + tid * 16;
        if (tid < 128) cp16(kDst[0], kg);
        #pragma unroll
        for (int u = 0; u < 4; u++) cp16(vDst[0] + u * 4096, vg + u * 4096);
        cp_commit();
    }

    float2 qv2[4];
    {
        const float4* qp = (const float4*)&g_q[((size_t)b * LPAD + l0 + tx) * 8];
        float4 q0 = qp[0], q1 = qp[1];
        qv2[0] = make_float2(q0.x, q0.y); qv2[1] = make_float2(q0.z, q0.w);
        qv2[2] = make_float2(q1.x, q1.y); qv2[3] = make_float2(q1.z, q1.w);
    }

    float mx = -1e30f, ssum = 0.f;
    float2 acc[4][2];
    #pragma unroll
    for (int i = 0; i < 4; i++) { acc[i][0] = make_float2(0.f, 0.f); acc[i][1] = make_float2(0.f, 0.f); }

    int buf = 0;
    for (int it = 0; it < NTILE; it++, buf ^= 1) {
        const int m0 = it * 64;

        cp_wait0();            // tile `it` resident (per-thread)
        __syncthreads();       // block-wide visibility; also closes prev accum

        const float* kCur = kS[buf];
        const float* vCur = vS[buf];
        const int mvalid = L_ - m0;

        // ---- scores: 16 j per thread, packed f32x2 dot ----
        float s[16];
        float lm = -1e30f;
        #pragma unroll
        for (int jj = 0; jj < 16; jj++) {
            int j = ty * 16 + jj;
            float4 k0 = *(const float4*)&kCur[j * 8];
            float4 k1 = *(const float4*)&kCur[j * 8 + 4];
            float2 t = fmul2(qv2[0], make_float2(k0.x, k0.y));
            t = ffma2(qv2[1], make_float2(k0.z, k0.w), t);
            t = ffma2(qv2[2], make_float2(k1.x, k1.y), t);
            t = ffma2(qv2[3], make_float2(k1.z, k1.w), t);
            float d = t.x + t.y;
            if (j >= mvalid) d = -1e30f;
            s[jj] = d;
            lm = fmaxf(lm, d);
        }
        lmS[ty * 64 + tx] = lm;
        __syncthreads();

        // ---- prefetch tile it+1 (safe: every thread passed its prev accum) ----
        if (it + 1 < NTILE) {
            const size_t mb = (size_t)b * LPAD + (it + 1) * 64;
            const char* kg = (const char*)&g_k[mb * 8] + tid * 16;
            const char* vg = (const char*)&g_v[mb * 64] + tid * 16;
            int nb = buf ^ 1;
            if (tid < 128) cp16(kDst[nb], kg);
            #pragma unroll
            for (int u = 0; u < 4; u++) cp16(vDst[nb] + u * 4096, vg + u * 4096);
        }
        cp_commit();

        float tmax = fmaxf(fmaxf(lmS[tx], lmS[64 + tx]), fmaxf(lmS[128 + tx], lmS[192 + tx]));
        float nmx  = fmaxf(mx, tmax);
        float corr = __expf(mx - nmx);
        mx = nmx;

        float ps = 0.f;
        #pragma unroll
        for (int jj = 0; jj < 16; jj++) {
            float p = __expf(s[jj] - nmx);
            ps += p;
            pT[(ty * 16 + jj) * 64 + tx] = p;   // transposed: [j][row]
        }
        psS[ty * 64 + tx] = ps;
        if (ty == 0) corrS[tx] = corr;
        __syncthreads();

        ssum = ssum * corr + psS[tx] + psS[64 + tx] + psS[128 + tx] + psS[192 + tx];

        // ---- tiled accum: rescale rows, then 4x4 tile ----
        {
            float cr0 = corrS[r0], cr1 = corrS[r0 + 1], cr2 = corrS[r0 + 2], cr3 = corrS[r0 + 3];
            acc[0][0].x *= cr0; acc[0][0].y *= cr0; acc[0][1].x *= cr0; acc[0][1].y *= cr0;
            acc[1][0].x *= cr1; acc[1][0].y *= cr1; acc[1][1].x *= cr1; acc[1][1].y *= cr1;
            acc[2][0].x *= cr2; acc[2][0].y *= cr2; acc[2][1].x *= cr2; acc[2][1].y *= cr2;
            acc[3][0].x *= cr3; acc[3][0].y *= cr3; acc[3][1].x *= cr3; acc[3][1].y *= cr3;
        }
        #pragma unroll 4
        for (int j = 0; j < 64; j++) {
            float4 p4 = *(const float4*)&pT[j * 64 + r0];
            float4 v4 = *(const float4*)&vCur[j * 64 + c0];
            float2 vlo = make_float2(v4.x, v4.y), vhi = make_float2(v4.z, v4.w);
            float2 pp0 = make_float2(p4.x, p4.x);
            float2 pp1 = make_float2(p4.y, p4.y);
            float2 pp2 = make_float2(p4.z, p4.z);
            float2 pp3 = make_float2(p4.w, p4.w);
            acc[0][0] = ffma2(pp0, vlo, acc[0][0]); acc[0][1] = ffma2(pp0, vhi, acc[0][1]);
            acc[1][0] = ffma2(pp1, vlo, acc[1][0]); acc[1][1] = ffma2(pp1, vhi, acc[1][1]);
            acc[2][0] = ffma2(pp2, vlo, acc[2][0]); acc[2][1] = ffma2(pp2, vhi, acc[2][1]);
            acc[3][0] = ffma2(pp3, vlo, acc[3][0]); acc[3][1] = ffma2(pp3, vhi, acc[3][1]);
        }
    }

    if (ty == 0) ssumS[tx] = ssum;
    __syncthreads();

    const float g = gamma[0];
    #pragma unroll
    for (int i = 0; i < 4; i++) {
        int row = r0 + i;
        int gl  = l0 + row;
        if (gl < L_) {
            float inv = 1.f / ssumS[row];
            float4 h4 = *(const float4*)&g_h[((size_t)b * LPAD + gl) * 64 + c0];
            float4 o;
            o.x = g * (acc[i][0].x * inv) + h4.x;
            o.y = g * (acc[i][0].y * inv) + h4.y;
            o.z = g * (acc[i][1].x * inv) + h4.z;
            o.w = g * (acc[i][1].y * inv) + h4.w;
            *(float4*)&out[((size_t)b * L_ + gl) * 64 + c0] = o;
        }
    }
}

// ---------------------------------------------------------------------------
extern "C" void kernel_launch(void* const* d_in, const int* in_sizes, int n_in,
                              void* d_out, int out_size)
{
    const float* X     = (const float*)d_in[0];
    const float* wA    = (const float*)d_in[1];
    const float* bA    = (const float*)d_in[2];
    const float* wB    = (const float*)d_in[3];
    const float* bB    = (const float*)d_in[4];
    const float* wq    = (const float*)d_in[5];
    const float* bq    = (const float*)d_in[6];
    const float* wk    = (const float*)d_in[7];
    const float* bk    = (const float*)d_in[8];
    const float* wv    = (const float*)d_in[9];
    const float* bv    = (const float*)d_in[10];
    const float* gamma = (const float*)d_in[11];
    float* out = (float*)d_out;

    const size_t smem1 = 17744 * sizeof(float);   // ~71KB
    cudaFuncSetAttribute(k1_conv_qkv, cudaFuncAttributeMaxDynamicSharedMemorySize, (int)smem1);

    dim3 grid(NTILE, B_);
    k0_transpose<<<48, 256>>>(wA, wB, wv);
    k1_conv_qkv<<<grid, 256, smem1>>>(X, bA, bB, wq, bq, wk, bk, bv);
    k2_attn<<<grid, 256>>>(gamma, out);
}

// round 7
// speedup vs baseline: 1.9493x; 1.1798x over previous
#include <cuda_runtime.h>
#include <cstdint>

#define B_   8
#define N_   207
#define T_   12
#define C_   64
#define L_   2484
#define LPAD 2496
#define NTILE 39

// ---------------- scratch (module globals) ----------------
__device__ float g_h[B_ * LPAD * C_];   // [b][l][c]
__device__ float g_q[B_ * LPAD * 8];    // [b][l][d]
__device__ float g_k[B_ * LPAD * 8];    // [b][m][d]
__device__ float g_v[B_ * LPAD * C_];   // [b][m][c]  (tf32-rounded fp32)
__device__ float g_wAT[192 * 64];       // [p=k*64+ci][c]
__device__ float g_wBT[192 * 64];
__device__ float g_wvT[64 * 64];        // [c][o]

// packed f32x2 FMA / MUL (Blackwell)
__device__ __forceinline__ float2 ffma2(float2 a, float2 b, float2 c) {
    float2 d;
    asm("fma.rn.f32x2 %0, %1, %2, %3;"
        : "=l"(reinterpret_cast<unsigned long long&>(d))
        : "l"(reinterpret_cast<unsigned long long&>(a)),
          "l"(reinterpret_cast<unsigned long long&>(b)),
          "l"(reinterpret_cast<unsigned long long&>(c)));
    return d;
}
__device__ __forceinline__ float2 fmul2(float2 a, float2 b) {
    float2 d;
    asm("mul.rn.f32x2 %0, %1, %2;"
        : "=l"(reinterpret_cast<unsigned long long&>(d))
        : "l"(reinterpret_cast<unsigned long long&>(a)),
          "l"(reinterpret_cast<unsigned long long&>(b)));
    return d;
}

__device__ __forceinline__ float to_tf32(float x) {
    unsigned r;
    asm("cvt.rna.tf32.f32 %0, %1;" : "=r"(r) : "f"(x));
    return __uint_as_float(r);
}

__device__ __forceinline__ void mma_tf32(float* d,
                                         unsigned a0, unsigned a1, unsigned a2, unsigned a3,
                                         unsigned b0, unsigned b1) {
    asm("mma.sync.aligned.m16n8k8.row.col.f32.tf32.tf32.f32 "
        "{%0,%1,%2,%3},{%4,%5,%6,%7},{%8,%9},{%0,%1,%2,%3};"
        : "+f"(d[0]), "+f"(d[1]), "+f"(d[2]), "+f"(d[3])
        : "r"(a0), "r"(a1), "r"(a2), "r"(a3), "r"(b0), "r"(b1));
}

__device__ __forceinline__ void cp16(unsigned int saddr, const void* gaddr) {
    asm volatile("cp.async.ca.shared.global [%0], [%1], 16;" :: "r"(saddr), "l"(gaddr));
}
__device__ __forceinline__ void cp_commit() {
    asm volatile("cp.async.commit_group;" ::: "memory");
}
__device__ __forceinline__ void cp_wait0() {
    asm volatile("cp.async.wait_group 0;" ::: "memory");
}

// ---------------------------------------------------------------------------
// Kernel 0: weight transposes (tiny, runs once per launch)
// ---------------------------------------------------------------------------
__global__ void k0_transpose(const float* __restrict__ wA,
                             const float* __restrict__ wB,
                             const float* __restrict__ wv)
{
    int t = blockIdx.x * 256 + threadIdx.x;
    if (t < 12288) {
        int p = t >> 6, c = t & 63;       // p = k*64 + ci
        int k = p >> 6, ci = p & 63;
        int src = (c * 64 + ci) * 3 + k;
        g_wAT[t] = wA[src];
        g_wBT[t] = wB[src];
    }
    if (t < 4096) {
        int c = t >> 6, o = t & 63;
        g_wvT[t] = wv[o * 64 + c];
    }
}

// ---------------------------------------------------------------------------
// Kernel 1: causal conv (x2) + GLU gate + q/k/v projections
// grid (NTILE, B), 256 threads, ~71KB dyn smem -> 3 blocks/SM
// ---------------------------------------------------------------------------
__global__ void __launch_bounds__(256, 3)
k1_conv_qkv(const float* __restrict__ X,
            const float* __restrict__ bA, const float* __restrict__ bB,
            const float* __restrict__ wq, const float* __restrict__ bq,
            const float* __restrict__ wk, const float* __restrict__ bk,
            const float* __restrict__ bv)
{
    extern __shared__ float smem[];
    float* xs  = smem;               // [l][pitch 193]  12352
    float* hs  = smem + 12352;       // [c][pitch 65]   4160
    float* wqS = smem + 16512;       // 512
    float* wkS = smem + 17024;       // 512
    float* bAs = smem + 17536;       // 64
    float* bBs = smem + 17600;       // 64
    float* bvS = smem + 17664;       // 64
    float* bqS = smem + 17728;       // 8
    float* bkS = smem + 17736;       // 8   total 17744 floats (~71KB)

    const int tid = threadIdx.x;
    const int b   = blockIdx.y;
    const int l0  = blockIdx.x * 64;

    // ---- stage small weights/biases ----
    { int e = tid;        wqS[e] = wq[e]; wkS[e] = wk[e];
      e = tid + 256;      wqS[e] = wq[e]; wkS[e] = wk[e]; }
    if (tid < 64)      { bAs[tid] = bA[tid]; bBs[tid] = bB[tid]; bvS[tid] = bv[tid]; }
    else if (tid < 72) { bqS[tid - 64] = bq[tid - 64]; bkS[tid - 64] = bk[tid - 64]; }

    // ---- stage conv taps: xs[l][k*64+ci] ----
    for (int e = tid; e < 64 * 192; e += 256) {
        int l = e / 192, r = e - l * 192;
        int k = r >> 6, ci = r & 63;
        int gl = l0 + l;
        float v = 0.f;
        if (gl < L_) {
            int n = gl / 12, t = gl - n * 12;
            int tt = t - 2 + k;
            if (tt >= 0) v = X[((b * N_ + n) * T_ + tt) * C_ + ci];
        }
        xs[l * 193 + r] = v;
    }
    __syncthreads();

    // ---- conv GEMM: 4c x 4l per thread, weights via LDG (L1-resident) ----
    const int cb = (tid & 15) * 4;
    const int lb = (tid >> 4) * 4;
    float2 aA[2][4], aB[2][4];
    #pragma unroll
    for (int i = 0; i < 2; i++)
        #pragma unroll
        for (int j = 0; j < 4; j++) { aA[i][j] = make_float2(0.f, 0.f); aB[i][j] = make_float2(0.f, 0.f); }

    #pragma unroll 4
    for (int p = 0; p < 192; p++) {
        float4 wa = __ldg((const float4*)&g_wAT[p * 64 + cb]);
        float4 wb = __ldg((const float4*)&g_wBT[p * 64 + cb]);
        float2 wa0 = make_float2(wa.x, wa.y), wa1 = make_float2(wa.z, wa.w);
        float2 wb0 = make_float2(wb.x, wb.y), wb1 = make_float2(wb.z, wb.w);
        #pragma unroll
        for (int j = 0; j < 4; j++) {
            float xv = xs[(lb + j) * 193 + p];
            float2 xx = make_float2(xv, xv);
            aA[0][j] = ffma2(wa0, xx, aA[0][j]);
            aA[1][j] = ffma2(wa1, xx, aA[1][j]);
            aB[0][j] = ffma2(wb0, xx, aB[0][j]);
            aB[1][j] = ffma2(wb1, xx, aB[1][j]);
        }
    }

    // ---- gate: h = (A+bA) * sigmoid(B+bB) -> hs[c][l] ----
    #pragma unroll
    for (int i2 = 0; i2 < 2; i2++) {
        int c0 = cb + i2 * 2;
        #pragma unroll
        for (int j = 0; j < 4; j++) {
            float a0 = aA[i2][j].x + bAs[c0];
            float a1 = aA[i2][j].y + bAs[c0 + 1];
            float g0 = aB[i2][j].x + bBs[c0];
            float g1 = aB[i2][j].y + bBs[c0 + 1];
            hs[c0 * 65 + lb + j]       = a0 / (1.f + __expf(-g0));
            hs[(c0 + 1) * 65 + lb + j] = a1 / (1.f + __expf(-g1));
        }
    }
    __syncthreads();

    // ---- write h to gmem as [b][l][c] ----
    for (int e = tid; e < 4096; e += 256) {
        int l = e >> 6, c = e & 63;
        int gl = l0 + l;
        if (gl < L_) g_h[((size_t)b * LPAD + gl) * 64 + c] = hs[c * 65 + l];
    }

    // ---- v = wv @ h + bv (4o x 4l per thread), stored tf32-rounded ----
    float2 vacc[2][4];
    #pragma unroll
    for (int i = 0; i < 2; i++)
        #pragma unroll
        for (int j = 0; j < 4; j++) vacc[i][j] = make_float2(0.f, 0.f);

    #pragma unroll 4
    for (int c = 0; c < 64; c++) {
        float4 w4 = __ldg((const float4*)&g_wvT[c * 64 + cb]);
        float2 w0 = make_float2(w4.x, w4.y), w1 = make_float2(w4.z, w4.w);
        #pragma unroll
        for (int j = 0; j < 4; j++) {
            float hv = hs[c * 65 + lb + j];
            float2 hh = make_float2(hv, hv);
            vacc[0][j] = ffma2(w0, hh, vacc[0][j]);
            vacc[1][j] = ffma2(w1, hh, vacc[1][j]);
        }
    }
    #pragma unroll
    for (int j = 0; j < 4; j++) {
        int gl = l0 + lb + j;
        float4 o;
        o.x = to_tf32(vacc[0][j].x + bvS[cb]);
        o.y = to_tf32(vacc[0][j].y + bvS[cb + 1]);
        o.z = to_tf32(vacc[1][j].x + bvS[cb + 2]);
        o.w = to_tf32(vacc[1][j].y + bvS[cb + 3]);
        if (gl >= L_) o = make_float4(0.f, 0.f, 0.f, 0.f);
        *(float4*)&g_v[((size_t)b * LPAD + gl) * 64 + cb] = o;
    }

    // ---- q,k: each thread one l, two d-values per tensor ----
    {
        int lq = tid & 63, dd = tid >> 6;       // dd 0..3 -> d=dd and d=dd+4
        float aq0 = 0.f, aq1 = 0.f, ak0 = 0.f, ak1 = 0.f;
        const float* wq0 = &wqS[dd * 64];       const float* wq1 = &wqS[(dd + 4) * 64];
        const float* wk0 = &wkS[dd * 64];       const float* wk1 = &wkS[(dd + 4) * 64];
        #pragma unroll 4
        for (int c = 0; c < 64; c++) {
            float hv = hs[c * 65 + lq];
            aq0 += wq0[c] * hv; aq1 += wq1[c] * hv;
            ak0 += wk0[c] * hv; ak1 += wk1[c] * hv;
        }
        int gl = l0 + lq;
        float q0 = aq0 + bqS[dd], q1 = aq1 + bqS[dd + 4];
        float k0 = ak0 + bkS[dd], k1 = ak1 + bkS[dd + 4];
        if (gl >= L_) { q0 = q1 = k0 = k1 = 0.f; }
        size_t base = ((size_t)b * LPAD + gl) * 8;
        g_q[base + dd] = q0; g_q[base + dd + 4] = q1;
        g_k[base + dd] = k0; g_k[base + dd + 4] = k1;
    }
}

// ---------------------------------------------------------------------------
// Kernel 2: flash attention; scalar QK^T + softmax, tensor-core (tf32) P@V.
// grid (NTILE, B), 256 threads, ~58KB dyn smem -> 3 blocks/SM
// smem layout (floats):
//   vS[2][64*68]  0     .. 8703   (pitch 68, conflict-free mma B loads)
//   pT[64*68]     8704  .. 13055  (P transposed [j][row], pitch 68)
//   kS[2][64*8]   13056 .. 14079
//   lmS[256]      14080, psS[256] 14336, corrS[64] 14592, ssumS[64] 14656
// total 14720 floats = 58880 B
// ---------------------------------------------------------------------------
__global__ void __launch_bounds__(256, 3)
k2_attn(const float* __restrict__ gamma, float* __restrict__ out)
{
    extern __shared__ float sm[];
    float* vS0   = sm;                // pitch 68
    float* vS1   = sm + 4352;
    float* pT    = sm + 8704;         // pitch 68
    float* kS0   = sm + 13056;        // pitch 8
    float* kS1   = sm + 13568;
    float* lmS   = sm + 14080;
    float* psS   = sm + 14336;
    float* corrS = sm + 14592;
    float* ssumS = sm + 14656;

    const int tid  = threadIdx.x;
    const int tx   = tid & 63;        // softmax view: query row
    const int ty   = tid >> 6;        // softmax view: j-quarter (16 j each)
    const int wid  = tid >> 5;
    const int lane = tid & 31;
    const int gid  = lane >> 2;       // mma group id (0..7)
    const int tq   = lane & 3;        // mma thread-in-group
    const int mw   = wid & 3;         // warp m-tile (16 rows)
    const int nw   = wid >> 2;        // warp n-half (32 cols)
    const int m0   = mw * 16;
    const int nbase = nw * 32;
    const int b    = blockIdx.y;
    const int l0   = blockIdx.x * 64;

    float* kS[2] = {kS0, kS1};
    float* vS[2] = {vS0, vS1};

    // cp.async smem byte addresses
    unsigned kBase[2], vBase[2];
    kBase[0] = (unsigned)__cvta_generic_to_shared(kS0);
    kBase[1] = (unsigned)__cvta_generic_to_shared(kS1);
    vBase[0] = (unsigned)__cvta_generic_to_shared(vS0);
    vBase[1] = (unsigned)__cvta_generic_to_shared(vS1);

    // prologue: tile 0 -> buf 0
    {
        const char* kg = (const char*)&g_k[((size_t)b * LPAD) * 8] + tid * 16;
        if (tid < 128) cp16(kBase[0] + tid * 16, kg);
        const char* vg = (const char*)&g_v[((size_t)b * LPAD) * 64];
        #pragma unroll
        for (int u = 0; u < 4; u++) {
            int e = tid + u * 256;            // 1024 chunks of 16B
            int row = e >> 4, cc = e & 15;
            cp16(vBase[0] + row * 272 + cc * 16, vg + row * 256 + cc * 16);
        }
        cp_commit();
    }

    float2 qv2[4];
    {
        const float4* qp = (const float4*)&g_q[((size_t)b * LPAD + l0 + tx) * 8];
        float4 q0 = qp[0], q1 = qp[1];
        qv2[0] = make_float2(q0.x, q0.y); qv2[1] = make_float2(q0.z, q0.w);
        qv2[2] = make_float2(q1.x, q1.y); qv2[3] = make_float2(q1.z, q1.w);
    }

    float mx = -1e30f, ssum = 0.f;
    float acc[4][4];                  // [n-tile][c-frag]
    #pragma unroll
    for (int i = 0; i < 4; i++)
        #pragma unroll
        for (int j = 0; j < 4; j++) acc[i][j] = 0.f;

    int buf = 0;
    for (int it = 0; it < NTILE; it++, buf ^= 1) {
        const int m0_tile = it * 64;

        cp_wait0();
        __syncthreads();              // tile resident + prev accum closed

        const float* kCur = kS[buf];
        const float* vCur = vS[buf];
        const int mvalid = L_ - m0_tile;

        // ---- scores: 16 j per thread, packed f32x2 dot ----
        float s[16];
        float lm = -1e30f;
        #pragma unroll
        for (int jj = 0; jj < 16; jj++) {
            int j = ty * 16 + jj;
            float4 k0 = *(const float4*)&kCur[j * 8];
            float4 k1 = *(const float4*)&kCur[j * 8 + 4];
            float2 t = fmul2(qv2[0], make_float2(k0.x, k0.y));
            t = ffma2(qv2[1], make_float2(k0.z, k0.w), t);
            t = ffma2(qv2[2], make_float2(k1.x, k1.y), t);
            t = ffma2(qv2[3], make_float2(k1.z, k1.w), t);
            float d = t.x + t.y;
            if (j >= mvalid) d = -1e30f;
            s[jj] = d;
            lm = fmaxf(lm, d);
        }
        lmS[ty * 64 + tx] = lm;
        __syncthreads();

        // ---- prefetch next tile ----
        if (it + 1 < NTILE) {
            const size_t mb = (size_t)b * LPAD + (it + 1) * 64;
            const char* kg = (const char*)&g_k[mb * 8] + tid * 16;
            const char* vg = (const char*)&g_v[mb * 64];
            int nb = buf ^ 1;
            if (tid < 128) cp16(kBase[nb] + tid * 16, kg);
            #pragma unroll
            for (int u = 0; u < 4; u++) {
                int e = tid + u * 256;
                int row = e >> 4, cc = e & 15;
                cp16(vBase[nb] + row * 272 + cc * 16, vg + row * 256 + cc * 16);
            }
        }
        cp_commit();

        float tmax = fmaxf(fmaxf(lmS[tx], lmS[64 + tx]), fmaxf(lmS[128 + tx], lmS[192 + tx]));
        float nmx  = fmaxf(mx, tmax);
        float corr = __expf(mx - nmx);
        mx = nmx;

        float ps = 0.f;
        #pragma unroll
        for (int jj = 0; jj < 16; jj++) {
            float p = to_tf32(__expf(s[jj] - nmx));
            ps += p;
            pT[(ty * 16 + jj) * 68 + tx] = p;   // [j][row], pitch 68
        }
        psS[ty * 64 + tx] = ps;
        if (ty == 0) corrS[tx] = corr;
        __syncthreads();

        ssum = ssum * corr + psS[tx] + psS[64 + tx] + psS[128 + tx] + psS[192 + tx];

        // ---- P@V on tensor cores: warp computes m16 x n32, k=64 in 8 steps ----
        {
            float cl = corrS[m0 + gid];
            float ch = corrS[m0 + gid + 8];
            #pragma unroll
            for (int nt = 0; nt < 4; nt++) {
                acc[nt][0] *= cl; acc[nt][1] *= cl;
                acc[nt][2] *= ch; acc[nt][3] *= ch;
            }
        }
        #pragma unroll
        for (int ks = 0; ks < 8; ks++) {
            const int k0 = ks * 8;
            unsigned a0 = __float_as_uint(pT[(k0 + tq) * 68 + m0 + gid]);
            unsigned a1 = __float_as_uint(pT[(k0 + tq) * 68 + m0 + gid + 8]);
            unsigned a2 = __float_as_uint(pT[(k0 + tq + 4) * 68 + m0 + gid]);
            unsigned a3 = __float_as_uint(pT[(k0 + tq + 4) * 68 + m0 + gid + 8]);
            #pragma unroll
            for (int nt = 0; nt < 4; nt++) {
                const int n0 = nbase + nt * 8;
                unsigned b0 = __float_as_uint(vCur[(k0 + tq) * 68 + n0 + gid]);
                unsigned b1 = __float_as_uint(vCur[(k0 + tq + 4) * 68 + n0 + gid]);
                mma_tf32(acc[nt], a0, a1, a2, a3, b0, b1);
            }
        }
    }

    if (ty == 0) ssumS[tx] = ssum;
    __syncthreads();

    // ---- epilogue: c-frag rows gid/gid+8, cols 2tq/2tq+1 per n-tile ----
    const float g = gamma[0];
    const int gl_lo = l0 + m0 + gid;
    const int gl_hi = gl_lo + 8;
    const float inv_lo = 1.f / ssumS[m0 + gid];
    const float inv_hi = 1.f / ssumS[m0 + gid + 8];
    #pragma unroll
    for (int nt = 0; nt < 4; nt++) {
        const int col = nbase + nt * 8 + 2 * tq;
        if (gl_lo < L_) {
            const float* hp = &g_h[((size_t)b * LPAD + gl_lo) * 64 + col];
            float2 h2 = *(const float2*)hp;
            float2 o;
            o.x = g * (acc[nt][0] * inv_lo) + h2.x;
            o.y = g * (acc[nt][1] * inv_lo) + h2.y;
            *(float2*)&out[((size_t)b * L_ + gl_lo) * 64 + col] = o;
        }
        if (gl_hi < L_) {
            const float* hp = &g_h[((size_t)b * LPAD + gl_hi) * 64 + col];
            float2 h2 = *(const float2*)hp;
            float2 o;
            o.x = g * (acc[nt][2] * inv_hi) + h2.x;
            o.y = g * (acc[nt][3] * inv_hi) + h2.y;
            *(float2*)&out[((size_t)b * L_ + gl_hi) * 64 + col] = o;
        }
    }
}

// ---------------------------------------------------------------------------
extern "C" void kernel_launch(void* const* d_in, const int* in_sizes, int n_in,
                              void* d_out, int out_size)
{
    const float* X     = (const float*)d_in[0];
    const float* wA    = (const float*)d_in[1];
    const float* bA    = (const float*)d_in[2];
    const float* wB    = (const float*)d_in[3];
    const float* bB    = (const float*)d_in[4];
    const float* wq    = (const float*)d_in[5];
    const float* bq    = (const float*)d_in[6];
    const float* wk    = (const float*)d_in[7];
    const float* bk    = (const float*)d_in[8];
    const float* wv    = (const float*)d_in[9];
    const float* bv    = (const float*)d_in[10];
    const float* gamma = (const float*)d_in[11];
    float* out = (float*)d_out;

    const size_t smem1 = 17744 * sizeof(float);   // ~71KB
    cudaFuncSetAttribute(k1_conv_qkv, cudaFuncAttributeMaxDynamicSharedMemorySize, (int)smem1);
    const size_t smem2 = 14720 * sizeof(float);   // ~58.9KB
    cudaFuncSetAttribute(k2_attn, cudaFuncAttributeMaxDynamicSharedMemorySize, (int)smem2);

    dim3 grid(NTILE, B_);
    k0_transpose<<<48, 256>>>(wA, wB, wv);
    k1_conv_qkv<<<grid, 256, smem1>>>(X, bA, bB, wq, bq, wk, bk, bv);
    k2_attn<<<grid, 256, smem2>>>(gamma, out);
}

// round 8
// speedup vs baseline: 2.3626x; 1.2121x over previous
#include <cuda_runtime.h>
#include <cstdint>

#define B_   8
#define N_   207
#define T_   12
#define C_   64
#define L_   2484
#define LPAD 2496
#define NTILE 39

// ---------------- scratch (module globals) ----------------
__device__ float g_h[B_ * LPAD * C_];   // [b][l][c]
__device__ float g_q[B_ * LPAD * 8];    // [b][l][d]  (tf32-rounded)
__device__ float g_k[B_ * LPAD * 8];    // [b][m][d]  (tf32-rounded)
__device__ float g_v[B_ * LPAD * C_];   // [b][m][c]  (tf32-rounded)
__device__ float g_wAT[192 * 64];       // [p=k*64+ci][c]
__device__ float g_wBT[192 * 64];
__device__ float g_wvT[64 * 64];        // [c][o]

// packed f32x2 FMA / MUL (Blackwell)
__device__ __forceinline__ float2 ffma2(float2 a, float2 b, float2 c) {
    float2 d;
    asm("fma.rn.f32x2 %0, %1, %2, %3;"
        : "=l"(reinterpret_cast<unsigned long long&>(d))
        : "l"(reinterpret_cast<unsigned long long&>(a)),
          "l"(reinterpret_cast<unsigned long long&>(b)),
          "l"(reinterpret_cast<unsigned long long&>(c)));
    return d;
}

__device__ __forceinline__ float to_tf32(float x) {
    unsigned r;
    asm("cvt.rna.tf32.f32 %0, %1;" : "=r"(r) : "f"(x));
    return __uint_as_float(r);
}

__device__ __forceinline__ void mma_tf32(float* d,
                                         unsigned a0, unsigned a1, unsigned a2, unsigned a3,
                                         unsigned b0, unsigned b1) {
    asm("mma.sync.aligned.m16n8k8.row.col.f32.tf32.tf32.f32 "
        "{%0,%1,%2,%3},{%4,%5,%6,%7},{%8,%9},{%0,%1,%2,%3};"
        : "+f"(d[0]), "+f"(d[1]), "+f"(d[2]), "+f"(d[3])
        : "r"(a0), "r"(a1), "r"(a2), "r"(a3), "r"(b0), "r"(b1));
}

__device__ __forceinline__ void cp16(unsigned int saddr, const void* gaddr) {
    asm volatile("cp.async.ca.shared.global [%0], [%1], 16;" :: "r"(saddr), "l"(gaddr));
}
__device__ __forceinline__ void cp_commit() {
    asm volatile("cp.async.commit_group;" ::: "memory");
}
__device__ __forceinline__ void cp_wait0() {
    asm volatile("cp.async.wait_group 0;" ::: "memory");
}

// ---------------------------------------------------------------------------
// Kernel 0: weight transposes (tiny, runs once per launch)
// ---------------------------------------------------------------------------
__global__ void k0_transpose(const float* __restrict__ wA,
                             const float* __restrict__ wB,
                             const float* __restrict__ wv)
{
    int t = blockIdx.x * 256 + threadIdx.x;
    if (t < 12288) {
        int p = t >> 6, c = t & 63;       // p = k*64 + ci
        int k = p >> 6, ci = p & 63;
        int src = (c * 64 + ci) * 3 + k;
        g_wAT[t] = wA[src];
        g_wBT[t] = wB[src];
    }
    if (t < 4096) {
        int c = t >> 6, o = t & 63;
        g_wvT[t] = wv[o * 64 + c];
    }
}

// ---------------------------------------------------------------------------
// Kernel 1: causal conv (x2) + GLU gate + q/k/v projections
// grid (NTILE, B), 256 threads, ~71KB dyn smem -> 3 blocks/SM
// ---------------------------------------------------------------------------
__global__ void __launch_bounds__(256, 3)
k1_conv_qkv(const float* __restrict__ X,
            const float* __restrict__ bA, const float* __restrict__ bB,
            const float* __restrict__ wq, const float* __restrict__ bq,
            const float* __restrict__ wk, const float* __restrict__ bk,
            const float* __restrict__ bv)
{
    extern __shared__ float smem[];
    float* xs  = smem;               // [l][pitch 193]  12352
    float* hs  = smem + 12352;       // [c][pitch 65]   4160
    float* wqS = smem + 16512;       // 512
    float* wkS = smem + 17024;       // 512
    float* bAs = smem + 17536;       // 64
    float* bBs = smem + 17600;       // 64
    float* bvS = smem + 17664;       // 64
    float* bqS = smem + 17728;       // 8
    float* bkS = smem + 17736;       // 8   total 17744 floats (~71KB)

    const int tid = threadIdx.x;
    const int b   = blockIdx.y;
    const int l0  = blockIdx.x * 64;

    // ---- stage small weights/biases ----
    { int e = tid;        wqS[e] = wq[e]; wkS[e] = wk[e];
      e = tid + 256;      wqS[e] = wq[e]; wkS[e] = wk[e]; }
    if (tid < 64)      { bAs[tid] = bA[tid]; bBs[tid] = bB[tid]; bvS[tid] = bv[tid]; }
    else if (tid < 72) { bqS[tid - 64] = bq[tid - 64]; bkS[tid - 64] = bk[tid - 64]; }

    // ---- stage conv taps: xs[l][k*64+ci] ----
    for (int e = tid; e < 64 * 192; e += 256) {
        int l = e / 192, r = e - l * 192;
        int k = r >> 6, ci = r & 63;
        int gl = l0 + l;
        float v = 0.f;
        if (gl < L_) {
            int n = gl / 12, t = gl - n * 12;
            int tt = t - 2 + k;
            if (tt >= 0) v = X[((b * N_ + n) * T_ + tt) * C_ + ci];
        }
        xs[l * 193 + r] = v;
    }
    __syncthreads();

    // ---- conv GEMM: 4c x 4l per thread, weights via LDG (L1-resident) ----
    const int cb = (tid & 15) * 4;
    const int lb = (tid >> 4) * 4;
    float2 aA[2][4], aB[2][4];
    #pragma unroll
    for (int i = 0; i < 2; i++)
        #pragma unroll
        for (int j = 0; j < 4; j++) { aA[i][j] = make_float2(0.f, 0.f); aB[i][j] = make_float2(0.f, 0.f); }

    #pragma unroll 4
    for (int p = 0; p < 192; p++) {
        float4 wa = __ldg((const float4*)&g_wAT[p * 64 + cb]);
        float4 wb = __ldg((const float4*)&g_wBT[p * 64 + cb]);
        float2 wa0 = make_float2(wa.x, wa.y), wa1 = make_float2(wa.z, wa.w);
        float2 wb0 = make_float2(wb.x, wb.y), wb1 = make_float2(wb.z, wb.w);
        #pragma unroll
        for (int j = 0; j < 4; j++) {
            float xv = xs[(lb + j) * 193 + p];
            float2 xx = make_float2(xv, xv);
            aA[0][j] = ffma2(wa0, xx, aA[0][j]);
            aA[1][j] = ffma2(wa1, xx, aA[1][j]);
            aB[0][j] = ffma2(wb0, xx, aB[0][j]);
            aB[1][j] = ffma2(wb1, xx, aB[1][j]);
        }
    }

    // ---- gate: h = (A+bA) * sigmoid(B+bB) -> hs[c][l] ----
    #pragma unroll
    for (int i2 = 0; i2 < 2; i2++) {
        int c0 = cb + i2 * 2;
        #pragma unroll
        for (int j = 0; j < 4; j++) {
            float a0 = aA[i2][j].x + bAs[c0];
            float a1 = aA[i2][j].y + bAs[c0 + 1];
            float g0 = aB[i2][j].x + bBs[c0];
            float g1 = aB[i2][j].y + bBs[c0 + 1];
            hs[c0 * 65 + lb + j]       = a0 / (1.f + __expf(-g0));
            hs[(c0 + 1) * 65 + lb + j] = a1 / (1.f + __expf(-g1));
        }
    }
    __syncthreads();

    // ---- write h to gmem as [b][l][c] ----
    for (int e = tid; e < 4096; e += 256) {
        int l = e >> 6, c = e & 63;
        int gl = l0 + l;
        if (gl < L_) g_h[((size_t)b * LPAD + gl) * 64 + c] = hs[c * 65 + l];
    }

    // ---- v = wv @ h + bv (4o x 4l per thread), stored tf32-rounded ----
    float2 vacc[2][4];
    #pragma unroll
    for (int i = 0; i < 2; i++)
        #pragma unroll
        for (int j = 0; j < 4; j++) vacc[i][j] = make_float2(0.f, 0.f);

    #pragma unroll 4
    for (int c = 0; c < 64; c++) {
        float4 w4 = __ldg((const float4*)&g_wvT[c * 64 + cb]);
        float2 w0 = make_float2(w4.x, w4.y), w1 = make_float2(w4.z, w4.w);
        #pragma unroll
        for (int j = 0; j < 4; j++) {
            float hv = hs[c * 65 + lb + j];
            float2 hh = make_float2(hv, hv);
            vacc[0][j] = ffma2(w0, hh, vacc[0][j]);
            vacc[1][j] = ffma2(w1, hh, vacc[1][j]);
        }
    }
    #pragma unroll
    for (int j = 0; j < 4; j++) {
        int gl = l0 + lb + j;
        float4 o;
        o.x = to_tf32(vacc[0][j].x + bvS[cb]);
        o.y = to_tf32(vacc[0][j].y + bvS[cb + 1]);
        o.z = to_tf32(vacc[1][j].x + bvS[cb + 2]);
        o.w = to_tf32(vacc[1][j].y + bvS[cb + 3]);
        if (gl >= L_) o = make_float4(0.f, 0.f, 0.f, 0.f);
        *(float4*)&g_v[((size_t)b * LPAD + gl) * 64 + cb] = o;
    }

    // ---- q,k: each thread one l, two d-values per tensor (tf32-rounded) ----
    {
        int lq = tid & 63, dd = tid >> 6;       // dd 0..3 -> d=dd and d=dd+4
        float aq0 = 0.f, aq1 = 0.f, ak0 = 0.f, ak1 = 0.f;
        const float* wq0 = &wqS[dd * 64];       const float* wq1 = &wqS[(dd + 4) * 64];
        const float* wk0 = &wkS[dd * 64];       const float* wk1 = &wkS[(dd + 4) * 64];
        #pragma unroll 4
        for (int c = 0; c < 64; c++) {
            float hv = hs[c * 65 + lq];
            aq0 += wq0[c] * hv; aq1 += wq1[c] * hv;
            ak0 += wk0[c] * hv; ak1 += wk1[c] * hv;
        }
        int gl = l0 + lq;
        float q0 = to_tf32(aq0 + bqS[dd]), q1 = to_tf32(aq1 + bqS[dd + 4]);
        float k0 = to_tf32(ak0 + bkS[dd]), k1 = to_tf32(ak1 + bkS[dd + 4]);
        if (gl >= L_) { q0 = q1 = k0 = k1 = 0.f; }
        size_t base = ((size_t)b * LPAD + gl) * 8;
        g_q[base + dd] = q0; g_q[base + dd + 4] = q1;
        g_k[base + dd] = k0; g_k[base + dd + 4] = k1;
    }
}

// ---------------------------------------------------------------------------
// Kernel 2: flash attention; tf32 mma for BOTH QK^T and P@V.
// grid (NTILE, B), 256 threads = 8 warps (mw 0..3, nw 0..1), 3 blocks/SM
// smem (floats):
//   vS[2][64*68] 0..8703  | pT[64*68] 8704..13055 | kS[2][64*12] 13056..14591
//   wmaxS[128] 14592 | wsumS[128] 14720 | mxS[2][64] 14848 | ssumS[64] 14976
// total 15040 floats = 60160 B
// ---------------------------------------------------------------------------
__global__ void __launch_bounds__(256, 3)
k2_attn(const float* __restrict__ gamma, float* __restrict__ out)
{
    extern __shared__ float sm[];
    float* vS0   = sm;                // pitch 68
    float* vS1   = sm + 4352;
    float* pT    = sm + 8704;         // pitch 68, [j][row]
    float* kS0   = sm + 13056;        // pitch 12 (conflict-free B-frag loads)
    float* kS1   = sm + 13824;
    float* wmaxS = sm + 14592;        // [nw][row]
    float* wsumS = sm + 14720;        // [nw][row]
    float* mxS   = sm + 14848;        // [par][row]
    float* ssumS = sm + 14976;        // [row]

    const int tid  = threadIdx.x;
    const int wid  = tid >> 5;
    const int lane = tid & 31;
    const int gid  = lane >> 2;       // 0..7
    const int tq   = lane & 3;        // 0..3
    const int mw   = wid & 3;         // warp m-tile (16 rows)
    const int nw   = wid >> 2;        // warp n-half (32 cols)
    const int m0   = mw * 16;
    const int nbase = nw * 32;
    const int b    = blockIdx.y;
    const int l0   = blockIdx.x * 64;

    const float* kS[2] = {kS0, kS1};
    const float* vS[2] = {vS0, vS1};

    unsigned kBase[2], vBase[2];
    kBase[0] = (unsigned)__cvta_generic_to_shared(kS0);
    kBase[1] = (unsigned)__cvta_generic_to_shared(kS1);
    vBase[0] = (unsigned)__cvta_generic_to_shared(vS0);
    vBase[1] = (unsigned)__cvta_generic_to_shared(vS1);

    // per-row running state init
    if (tid < 64) { mxS[tid] = -1e30f; ssumS[tid] = 0.f; }

    // prologue: tile 0 -> buf 0
    {
        const char* kg = (const char*)&g_k[((size_t)b * LPAD) * 8];
        if (tid < 128) {
            int row = tid >> 1, half = tid & 1;
            cp16(kBase[0] + row * 48 + half * 16, kg + row * 32 + half * 16);
        }
        const char* vg = (const char*)&g_v[((size_t)b * LPAD) * 64];
        #pragma unroll
        for (int u = 0; u < 4; u++) {
            int e = tid + u * 256;
            int row = e >> 4, cc = e & 15;
            cp16(vBase[0] + row * 272 + cc * 16, vg + row * 256 + cc * 16);
        }
        cp_commit();
    }

    // Q A-fragment (loop-invariant): rows l0+m0+gid(+8), cols tq(+4)
    unsigned qa0, qa1, qa2, qa3;
    {
        const float* qp = &g_q[((size_t)b * LPAD + l0 + m0) * 8];
        qa0 = __float_as_uint(qp[gid * 8 + tq]);
        qa1 = __float_as_uint(qp[(gid + 8) * 8 + tq]);
        qa2 = __float_as_uint(qp[gid * 8 + tq + 4]);
        qa3 = __float_as_uint(qp[(gid + 8) * 8 + tq + 4]);
    }

    float acc[4][4];
    #pragma unroll
    for (int i = 0; i < 4; i++)
        #pragma unroll
        for (int j = 0; j < 4; j++) acc[i][j] = 0.f;

    int buf = 0, par = 0;
    for (int it = 0; it < NTILE; it++, buf ^= 1, par ^= 1) {
        cp_wait0();
        __syncthreads();              // tile resident; prev tile fully consumed

        const float* kCur = kS[buf];
        const float* vCur = vS[buf];
        const int mvalid = L_ - it * 64;

        // ---- QK^T on tensor cores: s[nt] = Q(m16 k8) @ K^T(k8 n8) ----
        float s[4][4];
        #pragma unroll
        for (int nt = 0; nt < 4; nt++) {
            s[nt][0] = s[nt][1] = s[nt][2] = s[nt][3] = 0.f;
            const int n0 = nbase + nt * 8;
            unsigned b0 = __float_as_uint(kCur[(n0 + gid) * 12 + tq]);
            unsigned b1 = __float_as_uint(kCur[(n0 + gid) * 12 + tq + 4]);
            mma_tf32(s[nt], qa0, qa1, qa2, qa3, b0, b1);
        }

        // ---- prefetch next tile (safe: top sync passed) ----
        if (it + 1 < NTILE) {
            const size_t mb = (size_t)b * LPAD + (it + 1) * 64;
            const char* kg = (const char*)&g_k[mb * 8];
            const char* vg = (const char*)&g_v[mb * 64];
            int nb = buf ^ 1;
            if (tid < 128) {
                int row = tid >> 1, half = tid & 1;
                cp16(kBase[nb] + row * 48 + half * 16, kg + row * 32 + half * 16);
            }
            #pragma unroll
            for (int u = 0; u < 4; u++) {
                int e = tid + u * 256;
                int row = e >> 4, cc = e & 15;
                cp16(vBase[nb] + row * 272 + cc * 16, vg + row * 256 + cc * 16);
            }
        }
        cp_commit();

        // ---- mask (last tile only) ----
        if (mvalid < 64) {
            #pragma unroll
            for (int nt = 0; nt < 4; nt++) {
                int c0 = nbase + nt * 8 + 2 * tq;
                if (c0 >= mvalid)     { s[nt][0] = -1e30f; s[nt][2] = -1e30f; }
                if (c0 + 1 >= mvalid) { s[nt][1] = -1e30f; s[nt][3] = -1e30f; }
            }
        }

        // ---- warp row maxes (rows m0+gid, m0+gid+8 over this warp's 32 cols) ----
        float rlo = fmaxf(fmaxf(s[0][0], s[0][1]), fmaxf(s[1][0], s[1][1]));
        rlo = fmaxf(rlo, fmaxf(fmaxf(s[2][0], s[2][1]), fmaxf(s[3][0], s[3][1])));
        float rhi = fmaxf(fmaxf(s[0][2], s[0][3]), fmaxf(s[1][2], s[1][3]));
        rhi = fmaxf(rhi, fmaxf(fmaxf(s[2][2], s[2][3]), fmaxf(s[3][2], s[3][3])));
        rlo = fmaxf(rlo, __shfl_xor_sync(0xffffffff, rlo, 1));
        rlo = fmaxf(rlo, __shfl_xor_sync(0xffffffff, rlo, 2));
        rhi = fmaxf(rhi, __shfl_xor_sync(0xffffffff, rhi, 1));
        rhi = fmaxf(rhi, __shfl_xor_sync(0xffffffff, rhi, 2));
        if (tq == 0) {
            wmaxS[nw * 64 + m0 + gid]     = rlo;
            wmaxS[nw * 64 + m0 + gid + 8] = rhi;
        }
        __syncthreads();

        // ---- per-row corr / new max (computed redundantly by all 8 sharers) ----
        const int rlo_i = m0 + gid, rhi_i = m0 + gid + 8;
        float oldlo = mxS[par * 64 + rlo_i];
        float oldhi = mxS[par * 64 + rhi_i];
        float nmxlo = fmaxf(oldlo, fmaxf(wmaxS[rlo_i], wmaxS[64 + rlo_i]));
        float nmxhi = fmaxf(oldhi, fmaxf(wmaxS[rhi_i], wmaxS[64 + rhi_i]));
        float corrlo = __expf(oldlo - nmxlo);
        float corrhi = __expf(oldhi - nmxhi);
        if (nw == 0 && tq == 0) {
            mxS[(par ^ 1) * 64 + rlo_i] = nmxlo;
            mxS[(par ^ 1) * 64 + rhi_i] = nmxhi;
        }

        // ---- exp (tf32-rounded), transpose-store P, warp row sums ----
        float pslo = 0.f, pshi = 0.f;
        #pragma unroll
        for (int nt = 0; nt < 4; nt++) {
            const int col = nbase + nt * 8 + 2 * tq;
            #pragma unroll
            for (int e = 0; e < 2; e++) {
                float plo = to_tf32(__expf(s[nt][e]     - nmxlo));
                float phi = to_tf32(__expf(s[nt][2 + e] - nmxhi));
                pslo += plo; pshi += phi;
                pT[(col + e) * 68 + rlo_i] = plo;
                pT[(col + e) * 68 + rhi_i] = phi;
            }
        }
        pslo += __shfl_xor_sync(0xffffffff, pslo, 1);
        pslo += __shfl_xor_sync(0xffffffff, pslo, 2);
        pshi += __shfl_xor_sync(0xffffffff, pshi, 1);
        pshi += __shfl_xor_sync(0xffffffff, pshi, 2);
        if (tq == 0) {
            wsumS[nw * 64 + rlo_i] = pslo;
            wsumS[nw * 64 + rhi_i] = pshi;
        }
        __syncthreads();

        // ---- owner updates running denominator ----
        if (nw == 0 && tq == 0) {
            ssumS[rlo_i] = ssumS[rlo_i] * corrlo + wsumS[rlo_i] + wsumS[64 + rlo_i];
            ssumS[rhi_i] = ssumS[rhi_i] * corrhi + wsumS[rhi_i] + wsumS[64 + rhi_i];
        }

        // ---- rescale accumulators, P@V on tensor cores ----
        #pragma unroll
        for (int nt = 0; nt < 4; nt++) {
            acc[nt][0] *= corrlo; acc[nt][1] *= corrlo;
            acc[nt][2] *= corrhi; acc[nt][3] *= corrhi;
        }
        #pragma unroll
        for (int ks = 0; ks < 8; ks++) {
            const int k0 = ks * 8;
            unsigned a0 = __float_as_uint(pT[(k0 + tq) * 68 + m0 + gid]);
            unsigned a1 = __float_as_uint(pT[(k0 + tq) * 68 + m0 + gid + 8]);
            unsigned a2 = __float_as_uint(pT[(k0 + tq + 4) * 68 + m0 + gid]);
            unsigned a3 = __float_as_uint(pT[(k0 + tq + 4) * 68 + m0 + gid + 8]);
            #pragma unroll
            for (int nt = 0; nt < 4; nt++) {
                const int n0 = nbase + nt * 8;
                unsigned b0 = __float_as_uint(vCur[(k0 + tq) * 68 + n0 + gid]);
                unsigned b1 = __float_as_uint(vCur[(k0 + tq + 4) * 68 + n0 + gid]);
                mma_tf32(acc[nt], a0, a1, a2, a3, b0, b1);
            }
        }
    }

    __syncthreads();

    // ---- epilogue ----
    const float g = gamma[0];
    const int gl_lo = l0 + m0 + gid;
    const int gl_hi = gl_lo + 8;
    const float inv_lo = 1.f / ssumS[m0 + gid];
    const float inv_hi = 1.f / ssumS[m0 + gid + 8];
    #pragma unroll
    for (int nt = 0; nt < 4; nt++) {
        const int col = nbase + nt * 8 + 2 * tq;
        if (gl_lo < L_) {
            float2 h2 = *(const float2*)&g_h[((size_t)b * LPAD + gl_lo) * 64 + col];
            float2 o;
            o.x = g * (acc[nt][0] * inv_lo) + h2.x;
            o.y = g * (acc[nt][1] * inv_lo) + h2.y;
            *(float2*)&out[((size_t)b * L_ + gl_lo) * 64 + col] = o;
        }
        if (gl_hi < L_) {
            float2 h2 = *(const float2*)&g_h[((size_t)b * LPAD + gl_hi) * 64 + col];
            float2 o;
            o.x = g * (acc[nt][2] * inv_hi) + h2.x;
            o.y = g * (acc[nt][3] * inv_hi) + h2.y;
            *(float2*)&out[((size_t)b * L_ + gl_hi) * 64 + col] = o;
        }
    }
}

// ---------------------------------------------------------------------------
extern "C" void kernel_launch(void* const* d_in, const int* in_sizes, int n_in,
                              void* d_out, int out_size)
{
    const float* X     = (const float*)d_in[0];
    const float* wA    = (const float*)d_in[1];
    const float* bA    = (const float*)d_in[2];
    const float* wB    = (const float*)d_in[3];
    const float* bB    = (const float*)d_in[4];
    const float* wq    = (const float*)d_in[5];
    const float* bq    = (const float*)d_in[6];
    const float* wk    = (const float*)d_in[7];
    const float* bk    = (const float*)d_in[8];
    const float* wv    = (const float*)d_in[9];
    const float* bv    = (const float*)d_in[10];
    const float* gamma = (const float*)d_in[11];
    float* out = (float*)d_out;

    const size_t smem1 = 17744 * sizeof(float);   // ~71KB
    cudaFuncSetAttribute(k1_conv_qkv, cudaFuncAttributeMaxDynamicSharedMemorySize, (int)smem1);
    const size_t smem2 = 15040 * sizeof(float);   // ~60.2KB
    cudaFuncSetAttribute(k2_attn, cudaFuncAttributeMaxDynamicSharedMemorySize, (int)smem2);

    dim3 grid(NTILE, B_);
    k0_transpose<<<48, 256>>>(wA, wB, wv);
    k1_conv_qkv<<<grid, 256, smem1>>>(X, bA, bB, wq, bq, wk, bk, bv);
    k2_attn<<<grid, 256, smem2>>>(gamma, out);
}

// round 9
// speedup vs baseline: 2.8090x; 1.1889x over previous
#include <cuda_runtime.h>
#include <cstdint>

#define B_   8
#define N_   207
#define T_   12
#define C_   64
#define L_   2484
#define LPAD 2496
#define NTILE 39

// ---------------- scratch (module globals) ----------------
__device__ float g_h[B_ * LPAD * C_];   // [b][l][c]
__device__ float g_q[B_ * LPAD * 8];    // [b][l][d]  (tf32-rounded)
__device__ float g_k[B_ * LPAD * 8];    // [b][m][d]  (tf32-rounded)
__device__ float g_v[B_ * LPAD * C_];   // [b][m][c]  (tf32-rounded)
__device__ float g_wAT[192 * 64];       // [p=k*64+ci][c]
__device__ float g_wBT[192 * 64];
__device__ float g_wvT[64 * 64];        // [c][o]

// packed f32x2 FMA (Blackwell)
__device__ __forceinline__ float2 ffma2(float2 a, float2 b, float2 c) {
    float2 d;
    asm("fma.rn.f32x2 %0, %1, %2, %3;"
        : "=l"(reinterpret_cast<unsigned long long&>(d))
        : "l"(reinterpret_cast<unsigned long long&>(a)),
          "l"(reinterpret_cast<unsigned long long&>(b)),
          "l"(reinterpret_cast<unsigned long long&>(c)));
    return d;
}

__device__ __forceinline__ float to_tf32(float x) {
    unsigned r;
    asm("cvt.rna.tf32.f32 %0, %1;" : "=r"(r) : "f"(x));
    return __uint_as_float(r);
}

__device__ __forceinline__ void mma_tf32(float* d,
                                         unsigned a0, unsigned a1, unsigned a2, unsigned a3,
                                         unsigned b0, unsigned b1) {
    asm("mma.sync.aligned.m16n8k8.row.col.f32.tf32.tf32.f32 "
        "{%0,%1,%2,%3},{%4,%5,%6,%7},{%8,%9},{%0,%1,%2,%3};"
        : "+f"(d[0]), "+f"(d[1]), "+f"(d[2]), "+f"(d[3])
        : "r"(a0), "r"(a1), "r"(a2), "r"(a3), "r"(b0), "r"(b1));
}

__device__ __forceinline__ void cp16(unsigned int saddr, const void* gaddr) {
    asm volatile("cp.async.ca.shared.global [%0], [%1], 16;" :: "r"(saddr), "l"(gaddr));
}
__device__ __forceinline__ void cp_commit() {
    asm volatile("cp.async.commit_group;" ::: "memory");
}
__device__ __forceinline__ void cp_wait0() {
    asm volatile("cp.async.wait_group 0;" ::: "memory");
}

// ---------------------------------------------------------------------------
// Kernel 0: weight transposes (tiny, runs once per launch)
// ---------------------------------------------------------------------------
__global__ void k0_transpose(const float* __restrict__ wA,
                             const float* __restrict__ wB,
                             const float* __restrict__ wv)
{
    int t = blockIdx.x * 256 + threadIdx.x;
    if (t < 12288) {
        int p = t >> 6, c = t & 63;       // p = k*64 + ci
        int k = p >> 6, ci = p & 63;
        int src = (c * 64 + ci) * 3 + k;
        g_wAT[t] = wA[src];
        g_wBT[t] = wB[src];
    }
    if (t < 4096) {
        int c = t >> 6, o = t & 63;
        g_wvT[t] = wv[o * 64 + c];
    }
}

// ---------------------------------------------------------------------------
// Kernel 1: causal conv (x2) + GLU gate + q/k/v projections
// grid (NTILE, B), 256 threads, ~71KB dyn smem -> 3 blocks/SM
// ---------------------------------------------------------------------------
__global__ void __launch_bounds__(256, 3)
k1_conv_qkv(const float* __restrict__ X,
            const float* __restrict__ bA, const float* __restrict__ bB,
            const float* __restrict__ wq, const float* __restrict__ bq,
            const float* __restrict__ wk, const float* __restrict__ bk,
            const float* __restrict__ bv)
{
    extern __shared__ float smem[];
    float* xs  = smem;               // [l][pitch 193]  12352
    float* hs  = smem + 12352;       // [c][pitch 65]   4160
    float* wqS = smem + 16512;       // 512
    float* wkS = smem + 17024;       // 512
    float* bAs = smem + 17536;       // 64
    float* bBs = smem + 17600;       // 64
    float* bvS = smem + 17664;       // 64
    float* bqS = smem + 17728;       // 8
    float* bkS = smem + 17736;       // 8   total 17744 floats (~71KB)

    const int tid = threadIdx.x;
    const int b   = blockIdx.y;
    const int l0  = blockIdx.x * 64;

    // ---- stage small weights/biases ----
    { int e = tid;        wqS[e] = wq[e]; wkS[e] = wk[e];
      e = tid + 256;      wqS[e] = wq[e]; wkS[e] = wk[e]; }
    if (tid < 64)      { bAs[tid] = bA[tid]; bBs[tid] = bB[tid]; bvS[tid] = bv[tid]; }
    else if (tid < 72) { bqS[tid - 64] = bq[tid - 64]; bkS[tid - 64] = bk[tid - 64]; }

    // ---- stage conv taps: xs[l][k*64+ci] ----
    for (int e = tid; e < 64 * 192; e += 256) {
        int l = e / 192, r = e - l * 192;
        int k = r >> 6, ci = r & 63;
        int gl = l0 + l;
        float v = 0.f;
        if (gl < L_) {
            int n = gl / 12, t = gl - n * 12;
            int tt = t - 2 + k;
            if (tt >= 0) v = X[((b * N_ + n) * T_ + tt) * C_ + ci];
        }
        xs[l * 193 + r] = v;
    }
    __syncthreads();

    // ---- conv GEMM: 4c x 4l per thread, weights via LDG (L1-resident) ----
    const int cb = (tid & 15) * 4;
    const int lb = (tid >> 4) * 4;
    float2 aA[2][4], aB[2][4];
    #pragma unroll
    for (int i = 0; i < 2; i++)
        #pragma unroll
        for (int j = 0; j < 4; j++) { aA[i][j] = make_float2(0.f, 0.f); aB[i][j] = make_float2(0.f, 0.f); }

    #pragma unroll 4
    for (int p = 0; p < 192; p++) {
        float4 wa = __ldg((const float4*)&g_wAT[p * 64 + cb]);
        float4 wb = __ldg((const float4*)&g_wBT[p * 64 + cb]);
        float2 wa0 = make_float2(wa.x, wa.y), wa1 = make_float2(wa.z, wa.w);
        float2 wb0 = make_float2(wb.x, wb.y), wb1 = make_float2(wb.z, wb.w);
        #pragma unroll
        for (int j = 0; j < 4; j++) {
            float xv = xs[(lb + j) * 193 + p];
            float2 xx = make_float2(xv, xv);
            aA[0][j] = ffma2(wa0, xx, aA[0][j]);
            aA[1][j] = ffma2(wa1, xx, aA[1][j]);
            aB[0][j] = ffma2(wb0, xx, aB[0][j]);
            aB[1][j] = ffma2(wb1, xx, aB[1][j]);
        }
    }

    // ---- gate: h = (A+bA) * sigmoid(B+bB) -> hs[c][l] ----
    #pragma unroll
    for (int i2 = 0; i2 < 2; i2++) {
        int c0 = cb + i2 * 2;
        #pragma unroll
        for (int j = 0; j < 4; j++) {
            float a0 = aA[i2][j].x + bAs[c0];
            float a1 = aA[i2][j].y + bAs[c0 + 1];
            float g0 = aB[i2][j].x + bBs[c0];
            float g1 = aB[i2][j].y + bBs[c0 + 1];
            hs[c0 * 65 + lb + j]       = a0 / (1.f + __expf(-g0));
            hs[(c0 + 1) * 65 + lb + j] = a1 / (1.f + __expf(-g1));
        }
    }
    __syncthreads();

    // ---- write h to gmem as [b][l][c] ----
    for (int e = tid; e < 4096; e += 256) {
        int l = e >> 6, c = e & 63;
        int gl = l0 + l;
        if (gl < L_) g_h[((size_t)b * LPAD + gl) * 64 + c] = hs[c * 65 + l];
    }

    // ---- v = wv @ h + bv (4o x 4l per thread), stored tf32-rounded ----
    float2 vacc[2][4];
    #pragma unroll
    for (int i = 0; i < 2; i++)
        #pragma unroll
        for (int j = 0; j < 4; j++) vacc[i][j] = make_float2(0.f, 0.f);

    #pragma unroll 4
    for (int c = 0; c < 64; c++) {
        float4 w4 = __ldg((const float4*)&g_wvT[c * 64 + cb]);
        float2 w0 = make_float2(w4.x, w4.y), w1 = make_float2(w4.z, w4.w);
        #pragma unroll
        for (int j = 0; j < 4; j++) {
            float hv = hs[c * 65 + lb + j];
            float2 hh = make_float2(hv, hv);
            vacc[0][j] = ffma2(w0, hh, vacc[0][j]);
            vacc[1][j] = ffma2(w1, hh, vacc[1][j]);
        }
    }
    #pragma unroll
    for (int j = 0; j < 4; j++) {
        int gl = l0 + lb + j;
        float4 o;
        o.x = to_tf32(vacc[0][j].x + bvS[cb]);
        o.y = to_tf32(vacc[0][j].y + bvS[cb + 1]);
        o.z = to_tf32(vacc[1][j].x + bvS[cb + 2]);
        o.w = to_tf32(vacc[1][j].y + bvS[cb + 3]);
        if (gl >= L_) o = make_float4(0.f, 0.f, 0.f, 0.f);
        *(float4*)&g_v[((size_t)b * LPAD + gl) * 64 + cb] = o;
    }

    // ---- q,k: each thread one l, two d-values per tensor (tf32-rounded) ----
    {
        int lq = tid & 63, dd = tid >> 6;       // dd 0..3 -> d=dd and d=dd+4
        float aq0 = 0.f, aq1 = 0.f, ak0 = 0.f, ak1 = 0.f;
        const float* wq0 = &wqS[dd * 64];       const float* wq1 = &wqS[(dd + 4) * 64];
        const float* wk0 = &wkS[dd * 64];       const float* wk1 = &wkS[(dd + 4) * 64];
        #pragma unroll 4
        for (int c = 0; c < 64; c++) {
            float hv = hs[c * 65 + lq];
            aq0 += wq0[c] * hv; aq1 += wq1[c] * hv;
            ak0 += wk0[c] * hv; ak1 += wk1[c] * hv;
        }
        int gl = l0 + lq;
        float q0 = to_tf32(aq0 + bqS[dd]), q1 = to_tf32(aq1 + bqS[dd + 4]);
        float k0 = to_tf32(ak0 + bkS[dd]), k1 = to_tf32(ak1 + bkS[dd + 4]);
        if (gl >= L_) { q0 = q1 = k0 = k1 = 0.f; }
        size_t base = ((size_t)b * LPAD + gl) * 8;
        g_q[base + dd] = q0; g_q[base + dd + 4] = q1;
        g_k[base + dd] = k0; g_k[base + dd + 4] = k1;
    }
}

// ---------------------------------------------------------------------------
// Kernel 2: flash attention, warp-independent split-softmax streams.
// Warp (mw,nw): rows m0=mw*16..+15, key-cols kb=nw*32..+31 of every tile.
// Own running max/denominator in registers; merge streams once at the end.
// One __syncthreads per m-tile (buffers); pT stripes are warp-private.
// grid (NTILE, B), 256 threads, ~59.4KB smem, 3 blocks/SM
// ---------------------------------------------------------------------------
__global__ void __launch_bounds__(256, 3)
k2_attn(const float* __restrict__ gamma, float* __restrict__ out)
{
    extern __shared__ float sm[];
    float* vS0 = sm;                  // pitch 68
    float* vS1 = sm + 4352;
    float* pT  = sm + 8704;           // pitch 68; loop: [keycol][row] warp stripes; end: oS[row][col]
    float* kS0 = sm + 13056;          // pitch 12
    float* kS1 = sm + 13824;
    float* mxS = sm + 14592;          // [nw][64]
    float* ssS = sm + 14720;          // [nw][64]  (total 14848 floats)

    const int tid  = threadIdx.x;
    const int wid  = tid >> 5;
    const int lane = tid & 31;
    const int gid  = lane >> 2;       // 0..7
    const int tq   = lane & 3;        // 0..3
    const int mw   = wid & 3;         // row tile (16 rows)
    const int nw   = wid >> 2;        // key-column half
    const int m0   = mw * 16;
    const int kb   = nw * 32;
    const int b    = blockIdx.y;
    const int l0   = blockIdx.x * 64;

    const float* kS[2] = {kS0, kS1};
    const float* vS[2] = {vS0, vS1};

    unsigned kBase[2], vBase[2];
    kBase[0] = (unsigned)__cvta_generic_to_shared(kS0);
    kBase[1] = (unsigned)__cvta_generic_to_shared(kS1);
    vBase[0] = (unsigned)__cvta_generic_to_shared(vS0);
    vBase[1] = (unsigned)__cvta_generic_to_shared(vS1);

    // prologue: tile 0 -> buf 0
    {
        const char* kg = (const char*)&g_k[((size_t)b * LPAD) * 8];
        if (tid < 128) {
            int row = tid >> 1, half = tid & 1;
            cp16(kBase[0] + row * 48 + half * 16, kg + row * 32 + half * 16);
        }
        const char* vg = (const char*)&g_v[((size_t)b * LPAD) * 64];
        #pragma unroll
        for (int u = 0; u < 4; u++) {
            int e = tid + u * 256;
            int row = e >> 4, cc = e & 15;
            cp16(vBase[0] + row * 272 + cc * 16, vg + row * 256 + cc * 16);
        }
        cp_commit();
    }

    // Q A-fragment (loop-invariant)
    unsigned qa0, qa1, qa2, qa3;
    {
        const float* qp = &g_q[((size_t)b * LPAD + l0 + m0) * 8];
        qa0 = __float_as_uint(qp[gid * 8 + tq]);
        qa1 = __float_as_uint(qp[(gid + 8) * 8 + tq]);
        qa2 = __float_as_uint(qp[gid * 8 + tq + 4]);
        qa3 = __float_as_uint(qp[(gid + 8) * 8 + tq + 4]);
    }

    float acc[8][4];                  // m16 x n64 output fragment (full width)
    #pragma unroll
    for (int i = 0; i < 8; i++)
        #pragma unroll
        for (int j = 0; j < 4; j++) acc[i][j] = 0.f;

    float mxlo = -1e30f, mxhi = -1e30f, sslo = 0.f, sshi = 0.f;

    int buf = 0;
    for (int it = 0; it < NTILE; it++, buf ^= 1) {
        cp_wait0();
        __syncthreads();              // tile resident; prev tile consumed everywhere

        const float* kCur = kS[buf];
        const float* vCur = vS[buf];
        const int mvalid = L_ - it * 64;

        // ---- QK^T for this warp's 32 keys ----
        float s[4][4];
        #pragma unroll
        for (int nt = 0; nt < 4; nt++) {
            s[nt][0] = s[nt][1] = s[nt][2] = s[nt][3] = 0.f;
            const int key = kb + nt * 8 + gid;
            unsigned b0 = __float_as_uint(kCur[key * 12 + tq]);
            unsigned b1 = __float_as_uint(kCur[key * 12 + tq + 4]);
            mma_tf32(s[nt], qa0, qa1, qa2, qa3, b0, b1);
        }

        // ---- prefetch next tile ----
        if (it + 1 < NTILE) {
            const size_t mb = (size_t)b * LPAD + (it + 1) * 64;
            const char* kg = (const char*)&g_k[mb * 8];
            const char* vg = (const char*)&g_v[mb * 64];
            int nb = buf ^ 1;
            if (tid < 128) {
                int row = tid >> 1, half = tid & 1;
                cp16(kBase[nb] + row * 48 + half * 16, kg + row * 32 + half * 16);
            }
            #pragma unroll
            for (int u = 0; u < 4; u++) {
                int e = tid + u * 256;
                int row = e >> 4, cc = e & 15;
                cp16(vBase[nb] + row * 272 + cc * 16, vg + row * 256 + cc * 16);
            }
        }
        cp_commit();

        // ---- mask (last tile only) ----
        if (mvalid < 64) {
            #pragma unroll
            for (int nt = 0; nt < 4; nt++) {
                int c0 = kb + nt * 8 + 2 * tq;
                if (c0 >= mvalid)     { s[nt][0] = -1e30f; s[nt][2] = -1e30f; }
                if (c0 + 1 >= mvalid) { s[nt][1] = -1e30f; s[nt][3] = -1e30f; }
            }
        }

        // ---- warp-local row max / running rescale ----
        float rlo = fmaxf(fmaxf(s[0][0], s[0][1]), fmaxf(s[1][0], s[1][1]));
        rlo = fmaxf(rlo, fmaxf(fmaxf(s[2][0], s[2][1]), fmaxf(s[3][0], s[3][1])));
        float rhi = fmaxf(fmaxf(s[0][2], s[0][3]), fmaxf(s[1][2], s[1][3]));
        rhi = fmaxf(rhi, fmaxf(fmaxf(s[2][2], s[2][3]), fmaxf(s[3][2], s[3][3])));
        rlo = fmaxf(rlo, __shfl_xor_sync(0xffffffff, rlo, 1));
        rlo = fmaxf(rlo, __shfl_xor_sync(0xffffffff, rlo, 2));
        rhi = fmaxf(rhi, __shfl_xor_sync(0xffffffff, rhi, 1));
        rhi = fmaxf(rhi, __shfl_xor_sync(0xffffffff, rhi, 2));
        float nmxlo = fmaxf(mxlo, rlo);
        float nmxhi = fmaxf(mxhi, rhi);
        float corrlo = __expf(mxlo - nmxlo);
        float corrhi = __expf(mxhi - nmxhi);
        mxlo = nmxlo; mxhi = nmxhi;

        // ---- exp (tf32), store P stripe transposed, partial sums ----
        float pslo = 0.f, pshi = 0.f;
        #pragma unroll
        for (int nt = 0; nt < 4; nt++) {
            const int col = kb + nt * 8 + 2 * tq;
            #pragma unroll
            for (int e = 0; e < 2; e++) {
                float plo = to_tf32(__expf(s[nt][e]     - mxlo));
                float phi = to_tf32(__expf(s[nt][2 + e] - mxhi));
                pslo += plo; pshi += phi;
                pT[(col + e) * 68 + m0 + gid]     = plo;
                pT[(col + e) * 68 + m0 + gid + 8] = phi;
            }
        }
        pslo += __shfl_xor_sync(0xffffffff, pslo, 1);
        pslo += __shfl_xor_sync(0xffffffff, pslo, 2);
        pshi += __shfl_xor_sync(0xffffffff, pshi, 1);
        pshi += __shfl_xor_sync(0xffffffff, pshi, 2);
        sslo = sslo * corrlo + pslo;
        sshi = sshi * corrhi + pshi;

        // ---- rescale accumulators ----
        #pragma unroll
        for (int nt = 0; nt < 8; nt++) {
            acc[nt][0] *= corrlo; acc[nt][1] *= corrlo;
            acc[nt][2] *= corrhi; acc[nt][3] *= corrhi;
        }
        __syncwarp();

        // ---- P@V: 4 k-steps (this warp's keys), full n=64 output ----
        #pragma unroll
        for (int ks = 0; ks < 4; ks++) {
            const int kcol = kb + ks * 8;
            unsigned a0 = __float_as_uint(pT[(kcol + tq) * 68 + m0 + gid]);
            unsigned a1 = __float_as_uint(pT[(kcol + tq) * 68 + m0 + gid + 8]);
            unsigned a2 = __float_as_uint(pT[(kcol + tq + 4) * 68 + m0 + gid]);
            unsigned a3 = __float_as_uint(pT[(kcol + tq + 4) * 68 + m0 + gid + 8]);
            #pragma unroll
            for (int nt = 0; nt < 8; nt++) {
                const int n0 = nt * 8;
                unsigned b0 = __float_as_uint(vCur[(kcol + tq) * 68 + n0 + gid]);
                unsigned b1 = __float_as_uint(vCur[(kcol + tq + 4) * 68 + n0 + gid]);
                mma_tf32(acc[nt], a0, a1, a2, a3, b0, b1);
            }
        }
        __syncwarp();                 // stripe reads done before next iter's writes
    }

    // ---- split-softmax combine of the two key-half streams ----
    if (tq == 0) {
        mxS[nw * 64 + m0 + gid]     = mxlo;
        mxS[nw * 64 + m0 + gid + 8] = mxhi;
        ssS[nw * 64 + m0 + gid]     = sslo;
        ssS[nw * 64 + m0 + gid + 8] = sshi;
    }
    __syncthreads();

    const int rlo_i = m0 + gid, rhi_i = m0 + gid + 8;
    float Mlo = fmaxf(mxS[rlo_i], mxS[64 + rlo_i]);
    float Mhi = fmaxf(mxS[rhi_i], mxS[64 + rhi_i]);
    float denlo = ssS[rlo_i] * __expf(mxS[rlo_i] - Mlo) + ssS[64 + rlo_i] * __expf(mxS[64 + rlo_i] - Mlo);
    float denhi = ssS[rhi_i] * __expf(mxS[rhi_i] - Mhi) + ssS[64 + rhi_i] * __expf(mxS[64 + rhi_i] - Mhi);
    float sclo = __expf(mxlo - Mlo) / denlo;
    float schi = __expf(mxhi - Mhi) / denhi;

    // nw==0 deposits its scaled output into pT as oS[row][col] (pitch 68)
    if (nw == 0) {
        #pragma unroll
        for (int nt = 0; nt < 8; nt++) {
            const int col = nt * 8 + 2 * tq;
            pT[rlo_i * 68 + col]     = acc[nt][0] * sclo;
            pT[rlo_i * 68 + col + 1] = acc[nt][1] * sclo;
            pT[rhi_i * 68 + col]     = acc[nt][2] * schi;
            pT[rhi_i * 68 + col + 1] = acc[nt][3] * schi;
        }
    }
    __syncthreads();

    if (nw == 1) {
        const float g = gamma[0];
        const int gl_lo = l0 + rlo_i;
        const int gl_hi = l0 + rhi_i;
        #pragma unroll
        for (int nt = 0; nt < 8; nt++) {
            const int col = nt * 8 + 2 * tq;
            if (gl_lo < L_) {
                float2 h2 = *(const float2*)&g_h[((size_t)b * LPAD + gl_lo) * 64 + col];
                float2 o;
                o.x = g * (pT[rlo_i * 68 + col]     + acc[nt][0] * sclo) + h2.x;
                o.y = g * (pT[rlo_i * 68 + col + 1] + acc[nt][1] * sclo) + h2.y;
                *(float2*)&out[((size_t)b * L_ + gl_lo) * 64 + col] = o;
            }
            if (gl_hi < L_) {
                float2 h2 = *(const float2*)&g_h[((size_t)b * LPAD + gl_hi) * 64 + col];
                float2 o;
                o.x = g * (pT[rhi_i * 68 + col]     + acc[nt][2] * schi) + h2.x;
                o.y = g * (pT[rhi_i * 68 + col + 1] + acc[nt][3] * schi) + h2.y;
                *(float2*)&out[((size_t)b * L_ + gl_hi) * 64 + col] = o;
            }
        }
    }
}

// ---------------------------------------------------------------------------
extern "C" void kernel_launch(void* const* d_in, const int* in_sizes, int n_in,
                              void* d_out, int out_size)
{
    const float* X     = (const float*)d_in[0];
    const float* wA    = (const float*)d_in[1];
    const float* bA    = (const float*)d_in[2];
    const float* wB    = (const float*)d_in[3];
    const float* bB    = (const float*)d_in[4];
    const float* wq    = (const float*)d_in[5];
    const float* bq    = (const float*)d_in[6];
    const float* wk    = (const float*)d_in[7];
    const float* bk    = (const float*)d_in[8];
    const float* wv    = (const float*)d_in[9];
    const float* bv    = (const float*)d_in[10];
    const float* gamma = (const float*)d_in[11];
    float* out = (float*)d_out;

    const size_t smem1 = 17744 * sizeof(float);   // ~71KB
    cudaFuncSetAttribute(k1_conv_qkv, cudaFuncAttributeMaxDynamicSharedMemorySize, (int)smem1);
    const size_t smem2 = 14848 * sizeof(float);   // ~59.4KB
    cudaFuncSetAttribute(k2_attn, cudaFuncAttributeMaxDynamicSharedMemorySize, (int)smem2);

    dim3 grid(NTILE, B_);
    k0_transpose<<<48, 256>>>(wA, wB, wv);
    k1_conv_qkv<<<grid, 256, smem1>>>(X, bA, bB, wq, bq, wk, bk, bv);
    k2_attn<<<grid, 256, smem2>>>(gamma, out);
}

// round 10
// speedup vs baseline: 4.1294x; 1.4701x over previous
#include <cuda_runtime.h>
#include <cuda_bf16.h>
#include <cstdint>

#define B_   8
#define N_   207
#define T_   12
#define C_   64
#define L_   2484
#define LPAD 2496
#define NTILE 39

// ---------------- scratch (module globals) ----------------
__device__ float g_h[B_ * LPAD * C_];            // [b][l][c] fp32 (residual)
__device__ __nv_bfloat16 g_qb[B_ * LPAD * 8];    // [b][l][d]
__device__ __nv_bfloat16 g_kb[B_ * LPAD * 8];    // [b][m][d]
__device__ __nv_bfloat16 g_vb[B_ * 64 * LPAD];   // [b][c][m]  (transposed!)
__device__ float g_wAT[192 * 64];
__device__ float g_wBT[192 * 64];
__device__ float g_wvT[64 * 64];

// packed f32x2 FMA (Blackwell)
__device__ __forceinline__ float2 ffma2(float2 a, float2 b, float2 c) {
    float2 d;
    asm("fma.rn.f32x2 %0, %1, %2, %3;"
        : "=l"(reinterpret_cast<unsigned long long&>(d))
        : "l"(reinterpret_cast<unsigned long long&>(a)),
          "l"(reinterpret_cast<unsigned long long&>(b)),
          "l"(reinterpret_cast<unsigned long long&>(c)));
    return d;
}

__device__ __forceinline__ unsigned pack_bf16(float lo, float hi) {
    unsigned r;
    asm("cvt.rn.bf16x2.f32 %0, %1, %2;" : "=r"(r) : "f"(hi), "f"(lo));
    return r;
}

__device__ __forceinline__ void mma_bf16_k8(float* d, unsigned a0, unsigned a1, unsigned b0) {
    asm("mma.sync.aligned.m16n8k8.row.col.f32.bf16.bf16.f32 "
        "{%0,%1,%2,%3},{%4,%5},{%6},{%0,%1,%2,%3};"
        : "+f"(d[0]), "+f"(d[1]), "+f"(d[2]), "+f"(d[3])
        : "r"(a0), "r"(a1), "r"(b0));
}
__device__ __forceinline__ void mma_bf16_k16(float* d,
                                             unsigned a0, unsigned a1, unsigned a2, unsigned a3,
                                             unsigned b0, unsigned b1) {
    asm("mma.sync.aligned.m16n8k16.row.col.f32.bf16.bf16.f32 "
        "{%0,%1,%2,%3},{%4,%5,%6,%7},{%8,%9},{%0,%1,%2,%3};"
        : "+f"(d[0]), "+f"(d[1]), "+f"(d[2]), "+f"(d[3])
        : "r"(a0), "r"(a1), "r"(a2), "r"(a3), "r"(b0), "r"(b1));
}

__device__ __forceinline__ void cp16(unsigned int saddr, const void* gaddr) {
    asm volatile("cp.async.ca.shared.global [%0], [%1], 16;" :: "r"(saddr), "l"(gaddr));
}
__device__ __forceinline__ void cp_commit() {
    asm volatile("cp.async.commit_group;" ::: "memory");
}
__device__ __forceinline__ void cp_wait0() {
    asm volatile("cp.async.wait_group 0;" ::: "memory");
}

// ---------------------------------------------------------------------------
// Kernel 0: weight transposes
// ---------------------------------------------------------------------------
__global__ void k0_transpose(const float* __restrict__ wA,
                             const float* __restrict__ wB,
                             const float* __restrict__ wv)
{
    int t = blockIdx.x * 256 + threadIdx.x;
    if (t < 12288) {
        int p = t >> 6, c = t & 63;
        int k = p >> 6, ci = p & 63;
        int src = (c * 64 + ci) * 3 + k;
        g_wAT[t] = wA[src];
        g_wBT[t] = wB[src];
    }
    if (t < 4096) {
        int c = t >> 6, o = t & 63;
        g_wvT[t] = wv[o * 64 + c];
    }
}

// ---------------------------------------------------------------------------
// Kernel 1: causal conv (x2) + GLU gate + q/k/v projections
// grid (NTILE, B), 256 threads, ~71KB dyn smem -> 3 blocks/SM
// ---------------------------------------------------------------------------
__global__ void __launch_bounds__(256, 3)
k1_conv_qkv(const float* __restrict__ X,
            const float* __restrict__ bA, const float* __restrict__ bB,
            const float* __restrict__ wq, const float* __restrict__ bq,
            const float* __restrict__ wk, const float* __restrict__ bk,
            const float* __restrict__ bv)
{
    extern __shared__ float smem[];
    float* xs  = smem;               // [l][pitch 193]  12352
    float* hs  = smem + 12352;       // [c][pitch 65]   4160
    float* wqS = smem + 16512;       // 512
    float* wkS = smem + 17024;       // 512
    float* bAs = smem + 17536;
    float* bBs = smem + 17600;
    float* bvS = smem + 17664;
    float* bqS = smem + 17728;
    float* bkS = smem + 17736;       // total 17744 floats

    const int tid = threadIdx.x;
    const int b   = blockIdx.y;
    const int l0  = blockIdx.x * 64;

    { int e = tid;        wqS[e] = wq[e]; wkS[e] = wk[e];
      e = tid + 256;      wqS[e] = wq[e]; wkS[e] = wk[e]; }
    if (tid < 64)      { bAs[tid] = bA[tid]; bBs[tid] = bB[tid]; bvS[tid] = bv[tid]; }
    else if (tid < 72) { bqS[tid - 64] = bq[tid - 64]; bkS[tid - 64] = bk[tid - 64]; }

    for (int e = tid; e < 64 * 192; e += 256) {
        int l = e / 192, r = e - l * 192;
        int k = r >> 6, ci = r & 63;
        int gl = l0 + l;
        float v = 0.f;
        if (gl < L_) {
            int n = gl / 12, t = gl - n * 12;
            int tt = t - 2 + k;
            if (tt >= 0) v = X[((b * N_ + n) * T_ + tt) * C_ + ci];
        }
        xs[l * 193 + r] = v;
    }
    __syncthreads();

    const int cb = (tid & 15) * 4;
    const int lb = (tid >> 4) * 4;
    float2 aA[2][4], aB[2][4];
    #pragma unroll
    for (int i = 0; i < 2; i++)
        #pragma unroll
        for (int j = 0; j < 4; j++) { aA[i][j] = make_float2(0.f, 0.f); aB[i][j] = make_float2(0.f, 0.f); }

    #pragma unroll 4
    for (int p = 0; p < 192; p++) {
        float4 wa = __ldg((const float4*)&g_wAT[p * 64 + cb]);
        float4 wb = __ldg((const float4*)&g_wBT[p * 64 + cb]);
        float2 wa0 = make_float2(wa.x, wa.y), wa1 = make_float2(wa.z, wa.w);
        float2 wb0 = make_float2(wb.x, wb.y), wb1 = make_float2(wb.z, wb.w);
        #pragma unroll
        for (int j = 0; j < 4; j++) {
            float xv = xs[(lb + j) * 193 + p];
            float2 xx = make_float2(xv, xv);
            aA[0][j] = ffma2(wa0, xx, aA[0][j]);
            aA[1][j] = ffma2(wa1, xx, aA[1][j]);
            aB[0][j] = ffma2(wb0, xx, aB[0][j]);
            aB[1][j] = ffma2(wb1, xx, aB[1][j]);
        }
    }

    #pragma unroll
    for (int i2 = 0; i2 < 2; i2++) {
        int c0 = cb + i2 * 2;
        #pragma unroll
        for (int j = 0; j < 4; j++) {
            float a0 = aA[i2][j].x + bAs[c0];
            float a1 = aA[i2][j].y + bAs[c0 + 1];
            float g0 = aB[i2][j].x + bBs[c0];
            float g1 = aB[i2][j].y + bBs[c0 + 1];
            hs[c0 * 65 + lb + j]       = a0 / (1.f + __expf(-g0));
            hs[(c0 + 1) * 65 + lb + j] = a1 / (1.f + __expf(-g1));
        }
    }
    __syncthreads();

    for (int e = tid; e < 4096; e += 256) {
        int l = e >> 6, c = e & 63;
        int gl = l0 + l;
        if (gl < L_) g_h[((size_t)b * LPAD + gl) * 64 + c] = hs[c * 65 + l];
    }

    // ---- v = wv @ h + bv, stored bf16 TRANSPOSED [b][c][m] ----
    float2 vacc[2][4];
    #pragma unroll
    for (int i = 0; i < 2; i++)
        #pragma unroll
        for (int j = 0; j < 4; j++) vacc[i][j] = make_float2(0.f, 0.f);

    #pragma unroll 4
    for (int c = 0; c < 64; c++) {
        float4 w4 = __ldg((const float4*)&g_wvT[c * 64 + cb]);
        float2 w0 = make_float2(w4.x, w4.y), w1 = make_float2(w4.z, w4.w);
        #pragma unroll
        for (int j = 0; j < 4; j++) {
            float hv = hs[c * 65 + lb + j];
            float2 hh = make_float2(hv, hv);
            vacc[0][j] = ffma2(w0, hh, vacc[0][j]);
            vacc[1][j] = ffma2(w1, hh, vacc[1][j]);
        }
    }
    #pragma unroll
    for (int o = 0; o < 4; o++) {
        float r[4];
        #pragma unroll
        for (int j = 0; j < 4; j++) {
            float val = (o & 1) ? vacc[o >> 1][j].y : vacc[o >> 1][j].x;
            val += bvS[cb + o];
            if (l0 + lb + j >= L_) val = 0.f;
            r[j] = val;
        }
        size_t rowoff = ((size_t)(b * 64 + cb + o)) * LPAD + l0 + lb;
        *(unsigned*)(g_vb + rowoff)     = pack_bf16(r[0], r[1]);
        *(unsigned*)(g_vb + rowoff + 2) = pack_bf16(r[2], r[3]);
    }

    // ---- q,k: bf16 [b][l][8] ----
    {
        int lq = tid & 63, dd = tid >> 6;
        float aq0 = 0.f, aq1 = 0.f, ak0 = 0.f, ak1 = 0.f;
        const float* wq0 = &wqS[dd * 64];       const float* wq1 = &wqS[(dd + 4) * 64];
        const float* wk0 = &wkS[dd * 64];       const float* wk1 = &wkS[(dd + 4) * 64];
        #pragma unroll 4
        for (int c = 0; c < 64; c++) {
            float hv = hs[c * 65 + lq];
            aq0 += wq0[c] * hv; aq1 += wq1[c] * hv;
            ak0 += wk0[c] * hv; ak1 += wk1[c] * hv;
        }
        int gl = l0 + lq;
        float q0 = aq0 + bqS[dd], q1 = aq1 + bqS[dd + 4];
        float k0 = ak0 + bkS[dd], k1 = ak1 + bkS[dd + 4];
        if (gl >= L_) { q0 = q1 = k0 = k1 = 0.f; }
        size_t base = ((size_t)b * LPAD + gl) * 8;
        g_qb[base + dd]     = __float2bfloat16(q0);
        g_qb[base + dd + 4] = __float2bfloat16(q1);
        g_kb[base + dd]     = __float2bfloat16(k0);
        g_kb[base + dd + 4] = __float2bfloat16(k1);
    }
}

// ---------------------------------------------------------------------------
// Kernel 2: flash attention, bf16 mma, P kept in registers (FA2 fragment trick)
// Warp (mw,nw): rows m0=mw*16..+15, keys kb=nw*32..+31 per tile (split-softmax).
// grid (NTILE, B), 256 threads, ~38.4KB smem, 3 blocks/SM
// smem (words): vS[2][64*36] 0..4607 | kS[2][64*4] 4608..5119
//               mxS[128] 5120 | ssS[128] 5248 | oS[64*66] 5376..9599
// ---------------------------------------------------------------------------
__global__ void __launch_bounds__(256, 3)
k2_attn(const float* __restrict__ gamma, float* __restrict__ out)
{
    extern __shared__ float sm[];
    float* vS0 = sm;                  // [64 ch][36 words] bf16 pairs along keys
    float* vS1 = sm + 2304;
    float* kS0 = sm + 4608;           // [64 key][4 words] (8 bf16 per row)
    float* kS1 = sm + 4864;
    float* mxS = sm + 5120;           // [nw][64]
    float* ssS = sm + 5248;           // [nw][64]
    float* oS  = sm + 5376;           // [64][66] fp32 combine buffer

    const int tid  = threadIdx.x;
    const int wid  = tid >> 5;
    const int lane = tid & 31;
    const int gid  = lane >> 2;       // 0..7
    const int tq   = lane & 3;        // 0..3
    const int mw   = wid & 3;
    const int nw   = wid >> 2;
    const int m0   = mw * 16;
    const int kb   = nw * 32;
    const int b    = blockIdx.y;
    const int l0   = blockIdx.x * 64;

    const float* kS[2] = {kS0, kS1};
    const float* vS[2] = {vS0, vS1};

    unsigned kBase[2], vBase[2];
    kBase[0] = (unsigned)__cvta_generic_to_shared(kS0);
    kBase[1] = (unsigned)__cvta_generic_to_shared(kS1);
    vBase[0] = (unsigned)__cvta_generic_to_shared(vS0);
    vBase[1] = (unsigned)__cvta_generic_to_shared(vS1);

    // prologue: tile 0 -> buf 0
    {
        const char* kg = (const char*)g_kb + ((size_t)b * LPAD) * 16;
        if (tid < 64) cp16(kBase[0] + tid * 16, kg + tid * 16);
        const char* vg = (const char*)g_vb + ((size_t)b * 64 * LPAD) * 2;
        #pragma unroll
        for (int u = 0; u < 2; u++) {
            int e = tid + u * 256;                // 512 chunks of 16B
            int row = e >> 3, cc = e & 7;         // row = channel
            cp16(vBase[0] + row * 144 + cc * 16, vg + (size_t)row * (LPAD * 2) + cc * 16);
        }
        cp_commit();
    }

    // Q A-fragment (loop-invariant), bf16 pairs
    unsigned qa0, qa1;
    {
        const char* qrow = (const char*)g_qb + ((size_t)b * LPAD + l0 + m0) * 16;
        qa0 = *(const unsigned*)(qrow + gid * 16 + 4 * tq);
        qa1 = *(const unsigned*)(qrow + (gid + 8) * 16 + 4 * tq);
    }

    float acc[8][4];                  // m16 x n64 output fragment
    #pragma unroll
    for (int i = 0; i < 8; i++)
        #pragma unroll
        for (int j = 0; j < 4; j++) acc[i][j] = 0.f;

    float mxlo = -1e30f, mxhi = -1e30f, sslo = 0.f, sshi = 0.f;

    int buf = 0;
    for (int it = 0; it < NTILE; it++, buf ^= 1) {
        cp_wait0();
        __syncthreads();

        const char* kC = (const char*)kS[buf];
        const char* vC = (const char*)vS[buf];
        const int mvalid = L_ - it * 64;

        // ---- QK^T: 4 bf16 k8 mma for this warp's 32 keys ----
        float s[4][4];
        #pragma unroll
        for (int nt = 0; nt < 4; nt++) {
            s[nt][0] = s[nt][1] = s[nt][2] = s[nt][3] = 0.f;
            unsigned bb = *(const unsigned*)(kC + (kb + nt * 8 + gid) * 16 + 4 * tq);
            mma_bf16_k8(s[nt], qa0, qa1, bb);
        }

        // ---- prefetch next tile ----
        if (it + 1 < NTILE) {
            const size_t mnext = (size_t)(it + 1) * 64;
            const char* kg = (const char*)g_kb + ((size_t)b * LPAD + mnext) * 16;
            const char* vg = (const char*)g_vb + ((size_t)b * 64 * LPAD + mnext) * 2;
            int nb = buf ^ 1;
            if (tid < 64) cp16(kBase[nb] + tid * 16, kg + tid * 16);
            #pragma unroll
            for (int u = 0; u < 2; u++) {
                int e = tid + u * 256;
                int row = e >> 3, cc = e & 7;
                cp16(vBase[nb] + row * 144 + cc * 16, vg + (size_t)row * (LPAD * 2) + cc * 16);
            }
        }
        cp_commit();

        // ---- mask (last tile only) ----
        if (mvalid < 64) {
            #pragma unroll
            for (int nt = 0; nt < 4; nt++) {
                int c0 = kb + nt * 8 + 2 * tq;
                if (c0 >= mvalid)     { s[nt][0] = -1e30f; s[nt][2] = -1e30f; }
                if (c0 + 1 >= mvalid) { s[nt][1] = -1e30f; s[nt][3] = -1e30f; }
            }
        }

        // ---- warp-local row max / running rescale ----
        float rlo = fmaxf(fmaxf(s[0][0], s[0][1]), fmaxf(s[1][0], s[1][1]));
        rlo = fmaxf(rlo, fmaxf(fmaxf(s[2][0], s[2][1]), fmaxf(s[3][0], s[3][1])));
        float rhi = fmaxf(fmaxf(s[0][2], s[0][3]), fmaxf(s[1][2], s[1][3]));
        rhi = fmaxf(rhi, fmaxf(fmaxf(s[2][2], s[2][3]), fmaxf(s[3][2], s[3][3])));
        rlo = fmaxf(rlo, __shfl_xor_sync(0xffffffff, rlo, 1));
        rlo = fmaxf(rlo, __shfl_xor_sync(0xffffffff, rlo, 2));
        rhi = fmaxf(rhi, __shfl_xor_sync(0xffffffff, rhi, 1));
        rhi = fmaxf(rhi, __shfl_xor_sync(0xffffffff, rhi, 2));
        float nmxlo = fmaxf(mxlo, rlo);
        float nmxhi = fmaxf(mxhi, rhi);
        float corrlo = __expf(mxlo - nmxlo);
        float corrhi = __expf(mxhi - nmxhi);
        mxlo = nmxlo; mxhi = nmxhi;

        // ---- exp in place (fp32), warp row sums ----
        float pslo = 0.f, pshi = 0.f;
        #pragma unroll
        for (int nt = 0; nt < 4; nt++) {
            s[nt][0] = __expf(s[nt][0] - mxlo);
            s[nt][1] = __expf(s[nt][1] - mxlo);
            s[nt][2] = __expf(s[nt][2] - mxhi);
            s[nt][3] = __expf(s[nt][3] - mxhi);
            pslo += s[nt][0] + s[nt][1];
            pshi += s[nt][2] + s[nt][3];
        }
        pslo += __shfl_xor_sync(0xffffffff, pslo, 1);
        pslo += __shfl_xor_sync(0xffffffff, pslo, 2);
        pshi += __shfl_xor_sync(0xffffffff, pshi, 1);
        pshi += __shfl_xor_sync(0xffffffff, pshi, 2);
        sslo = sslo * corrlo + pslo;
        sshi = sshi * corrhi + pshi;

        // ---- pack P into bf16 A-fragments (registers only, no smem!) ----
        unsigned pa[2][4];
        pa[0][0] = pack_bf16(s[0][0], s[0][1]);   // row gid,   keys kb+2tq..+1
        pa[0][1] = pack_bf16(s[0][2], s[0][3]);   // row gid+8
        pa[0][2] = pack_bf16(s[1][0], s[1][1]);   // row gid,   keys kb+8+2tq..
        pa[0][3] = pack_bf16(s[1][2], s[1][3]);
        pa[1][0] = pack_bf16(s[2][0], s[2][1]);
        pa[1][1] = pack_bf16(s[2][2], s[2][3]);
        pa[1][2] = pack_bf16(s[3][0], s[3][1]);
        pa[1][3] = pack_bf16(s[3][2], s[3][3]);

        // ---- rescale accumulators ----
        #pragma unroll
        for (int nt = 0; nt < 8; nt++) {
            acc[nt][0] *= corrlo; acc[nt][1] *= corrlo;
            acc[nt][2] *= corrhi; acc[nt][3] *= corrhi;
        }

        // ---- P@V: 2 bf16 k16 steps x 8 channel tiles ----
        #pragma unroll
        for (int ks = 0; ks < 2; ks++) {
            const int kw = (kb >> 1) + ks * 8;    // word offset of key pair base
            #pragma unroll
            for (int nt = 0; nt < 8; nt++) {
                const char* vrow = vC + (nt * 8 + gid) * 144;
                unsigned b0 = *(const unsigned*)(vrow + (kw + tq) * 4);
                unsigned b1 = *(const unsigned*)(vrow + (kw + tq) * 4 + 16);
                mma_bf16_k16(acc[nt], pa[ks][0], pa[ks][1], pa[ks][2], pa[ks][3], b0, b1);
            }
        }
    }

    // ---- split-softmax combine of the two key-half streams ----
    if (tq == 0) {
        mxS[nw * 64 + m0 + gid]     = mxlo;
        mxS[nw * 64 + m0 + gid + 8] = mxhi;
        ssS[nw * 64 + m0 + gid]     = sslo;
        ssS[nw * 64 + m0 + gid + 8] = sshi;
    }
    __syncthreads();

    const int rlo_i = m0 + gid, rhi_i = m0 + gid + 8;
    float Mlo = fmaxf(mxS[rlo_i], mxS[64 + rlo_i]);
    float Mhi = fmaxf(mxS[rhi_i], mxS[64 + rhi_i]);
    float denlo = ssS[rlo_i] * __expf(mxS[rlo_i] - Mlo) + ssS[64 + rlo_i] * __expf(mxS[64 + rlo_i] - Mlo);
    float denhi = ssS[rhi_i] * __expf(mxS[rhi_i] - Mhi) + ssS[64 + rhi_i] * __expf(mxS[64 + rhi_i] - Mhi);
    float sclo = __expf(mxlo - Mlo) / denlo;
    float schi = __expf(mxhi - Mhi) / denhi;

    if (nw == 0) {
        #pragma unroll
        for (int nt = 0; nt < 8; nt++) {
            const int col = nt * 8 + 2 * tq;
            oS[rlo_i * 66 + col]     = acc[nt][0] * sclo;
            oS[rlo_i * 66 + col + 1] = acc[nt][1] * sclo;
            oS[rhi_i * 66 + col]     = acc[nt][2] * schi;
            oS[rhi_i * 66 + col + 1] = acc[nt][3] * schi;
        }
    }
    __syncthreads();

    if (nw == 1) {
        const float g = gamma[0];
        const int gl_lo = l0 + rlo_i;
        const int gl_hi = l0 + rhi_i;
        #pragma unroll
        for (int nt = 0; nt < 8; nt++) {
            const int col = nt * 8 + 2 * tq;
            if (gl_lo < L_) {
                float2 h2 = *(const float2*)&g_h[((size_t)b * LPAD + gl_lo) * 64 + col];
                float2 o;
                o.x = g * (oS[rlo_i * 66 + col]     + acc[nt][0] * sclo) + h2.x;
                o.y = g * (oS[rlo_i * 66 + col + 1] + acc[nt][1] * sclo) + h2.y;
                *(float2*)&out[((size_t)b * L_ + gl_lo) * 64 + col] = o;
            }
            if (gl_hi < L_) {
                float2 h2 = *(const float2*)&g_h[((size_t)b * LPAD + gl_hi) * 64 + col];
                float2 o;
                o.x = g * (oS[rhi_i * 66 + col]     + acc[nt][2] * schi) + h2.x;
                o.y = g * (oS[rhi_i * 66 + col + 1] + acc[nt][3] * schi) + h2.y;
                *(float2*)&out[((size_t)b * L_ + gl_hi) * 64 + col] = o;
            }
        }
    }
}

// ---------------------------------------------------------------------------
extern "C" void kernel_launch(void* const* d_in, const int* in_sizes, int n_in,
                              void* d_out, int out_size)
{
    const float* X     = (const float*)d_in[0];
    const float* wA    = (const float*)d_in[1];
    const float* bA    = (const float*)d_in[2];
    const float* wB    = (const float*)d_in[3];
    const float* bB    = (const float*)d_in[4];
    const float* wq    = (const float*)d_in[5];
    const float* bq    = (const float*)d_in[6];
    const float* wk    = (const float*)d_in[7];
    const float* bk    = (const float*)d_in[8];
    const float* wv    = (const float*)d_in[9];
    const float* bv    = (const float*)d_in[10];
    const float* gamma = (const float*)d_in[11];
    float* out = (float*)d_out;

    const size_t smem1 = 17744 * sizeof(float);   // ~71KB
    cudaFuncSetAttribute(k1_conv_qkv, cudaFuncAttributeMaxDynamicSharedMemorySize, (int)smem1);
    const size_t smem2 = 9600 * sizeof(float);    // ~38.4KB
    cudaFuncSetAttribute(k2_attn, cudaFuncAttributeMaxDynamicSharedMemorySize, (int)smem2);

    dim3 grid(NTILE, B_);
    k0_transpose<<<48, 256>>>(wA, wB, wv);
    k1_conv_qkv<<<grid, 256, smem1>>>(X, bA, bB, wq, bq, wk, bk, bv);
    k2_attn<<<grid, 256, smem2>>>(gamma, out);
}